// round 1
// baseline (speedup 1.0000x reference)
#include <cuda_runtime.h>
#include <math.h>

// VanillaRNN: h_t = tanh(W_hh @ h_{t-1} + W_hx @ x_t + b_h), out = W_hy^T @ h_T + b_p
// H = 2048, B = 2048, T = 64, C = 10
//
// Inputs (metadata order): x[B,T], W_hx[H,1], W_hh[H,H], W_hy[H,C], b_h[H,1], b_p[C,1]
// Output: [B, C] float32.

#define HD 2048
#define BD 2048
#define TD 64
#define CD 10

#define BM 128
#define BN 128
#define BK 16
#define NTHREADS 256
#define KTILES (HD / BK)   // 128

// Scratch: ping-pong hidden state buffers [H, B] + split-K partials for the output proj.
__device__ float g_h[2][(size_t)HD * BD];
__device__ float g_part[16 * (size_t)BD * CD];

// ---------------------------------------------------------------------------
// Step kernel: hout[m, n] = tanh( sum_k Whh[m,k] * hin[k,n] + Whx[m]*x[n,t] + bh[m] )
// Classic SIMT fp32 GEMM: 128x128 CTA tile, 8x8 per thread, BK=16,
// double-buffered smem + register prefetch. Fused rank-1 + bias + tanh epilogue.
// ---------------------------------------------------------------------------
__global__ __launch_bounds__(NTHREADS, 2)
void rnn_step(const float* __restrict__ Whh,
              const float* __restrict__ hin,
              const float* __restrict__ Whx,
              const float* __restrict__ xin,
              const float* __restrict__ bh,
              float* __restrict__ hout,
              int t)
{
    __shared__ float As[2][BK][BM];   // A transposed: As[k][m]
    __shared__ float Bs[2][BK][BN];   // B direct:     Bs[k][n]
    __shared__ float xsh[BN];
    __shared__ float wxh[BM];
    __shared__ float bhh[BM];

    const int tid = threadIdx.x;
    const int m0 = blockIdx.y * BM;
    const int n0 = blockIdx.x * BN;

    // Epilogue vectors into shared (covered by the first __syncthreads below).
    if (tid < BN) {
        xsh[tid] = xin[(size_t)(n0 + tid) * TD + t];
    } else {
        int r = tid - BN;
        wxh[r] = Whx[m0 + r];
        bhh[r] = bh[m0 + r];
    }

    // Global->shared loader mapping.
    const int a_row = tid >> 2;            // 0..63 (and +64 for second half)
    const int a_c4  = (tid & 3) << 2;      // 0,4,8,12 (k offset)
    const int b_kr  = tid >> 5;            // 0..7 (and +8)
    const int b_nc  = (tid & 31) << 2;     // 0..124

    const float* Ag = Whh + (size_t)(m0 + a_row) * HD + a_c4;
    const float* Bg = hin + (size_t)b_kr * BD + n0 + b_nc;

    // Load first K-tile.
    float4 a0 = *(const float4*)(Ag);
    float4 a1 = *(const float4*)(Ag + (size_t)64 * HD);
    float4 b0 = *(const float4*)(Bg);
    float4 b1 = *(const float4*)(Bg + (size_t)8 * BD);

    As[0][a_c4 + 0][a_row] = a0.x;
    As[0][a_c4 + 1][a_row] = a0.y;
    As[0][a_c4 + 2][a_row] = a0.z;
    As[0][a_c4 + 3][a_row] = a0.w;
    As[0][a_c4 + 0][a_row + 64] = a1.x;
    As[0][a_c4 + 1][a_row + 64] = a1.y;
    As[0][a_c4 + 2][a_row + 64] = a1.z;
    As[0][a_c4 + 3][a_row + 64] = a1.w;
    *(float4*)&Bs[0][b_kr][b_nc]     = b0;
    *(float4*)&Bs[0][b_kr + 8][b_nc] = b1;
    __syncthreads();

    float acc[8][8];
#pragma unroll
    for (int i = 0; i < 8; ++i)
#pragma unroll
        for (int j = 0; j < 8; ++j) acc[i][j] = 0.0f;

    const int tx4 = (tid & 15) << 2;   // output cols n = tx4+{0..3}, tx4+64+{0..3}
    const int ty4 = (tid >> 4) << 2;   // output rows m = ty4+{0..3}, ty4+64+{0..3}

    int buf = 0;
    for (int kt = 0; kt < KTILES; ++kt) {
        // Prefetch next K-tile into registers while computing the current one.
        if (kt + 1 < KTILES) {
            const float* Ag2 = Ag + (kt + 1) * BK;
            const float* Bg2 = Bg + (size_t)(kt + 1) * BK * BD;
            a0 = *(const float4*)(Ag2);
            a1 = *(const float4*)(Ag2 + (size_t)64 * HD);
            b0 = *(const float4*)(Bg2);
            b1 = *(const float4*)(Bg2 + (size_t)8 * BD);
        }

#pragma unroll
        for (int kk = 0; kk < BK; ++kk) {
            float4 ra0 = *(const float4*)&As[buf][kk][ty4];
            float4 ra1 = *(const float4*)&As[buf][kk][ty4 + 64];
            float4 rb0 = *(const float4*)&Bs[buf][kk][tx4];
            float4 rb1 = *(const float4*)&Bs[buf][kk][tx4 + 64];
            float am[8] = {ra0.x, ra0.y, ra0.z, ra0.w, ra1.x, ra1.y, ra1.z, ra1.w};
            float bn[8] = {rb0.x, rb0.y, rb0.z, rb0.w, rb1.x, rb1.y, rb1.z, rb1.w};
#pragma unroll
            for (int i = 0; i < 8; ++i)
#pragma unroll
                for (int j = 0; j < 8; ++j) acc[i][j] += am[i] * bn[j];
        }

        if (kt + 1 < KTILES) {
            const int nb = buf ^ 1;
            As[nb][a_c4 + 0][a_row] = a0.x;
            As[nb][a_c4 + 1][a_row] = a0.y;
            As[nb][a_c4 + 2][a_row] = a0.z;
            As[nb][a_c4 + 3][a_row] = a0.w;
            As[nb][a_c4 + 0][a_row + 64] = a1.x;
            As[nb][a_c4 + 1][a_row + 64] = a1.y;
            As[nb][a_c4 + 2][a_row + 64] = a1.z;
            As[nb][a_c4 + 3][a_row + 64] = a1.w;
            *(float4*)&Bs[nb][b_kr][b_nc]     = b0;
            *(float4*)&Bs[nb][b_kr + 8][b_nc] = b1;
            __syncthreads();
            buf = nb;
        }
    }

    // Fused epilogue: rank-1 x-term + bias + tanh, vectorized stores.
#pragma unroll
    for (int i = 0; i < 8; ++i) {
        const int m = (i < 4) ? (ty4 + i) : (ty4 + 64 + (i - 4));
        const float wx = wxh[m];
        const float bb = bhh[m];
        float* orow = hout + (size_t)(m0 + m) * BD + n0;
        float4 o;
        o.x = tanhf(acc[i][0] + wx * xsh[tx4 + 0] + bb);
        o.y = tanhf(acc[i][1] + wx * xsh[tx4 + 1] + bb);
        o.z = tanhf(acc[i][2] + wx * xsh[tx4 + 2] + bb);
        o.w = tanhf(acc[i][3] + wx * xsh[tx4 + 3] + bb);
        *(float4*)(orow + tx4) = o;
        o.x = tanhf(acc[i][4] + wx * xsh[tx4 + 64 + 0] + bb);
        o.y = tanhf(acc[i][5] + wx * xsh[tx4 + 64 + 1] + bb);
        o.z = tanhf(acc[i][6] + wx * xsh[tx4 + 64 + 2] + bb);
        o.w = tanhf(acc[i][7] + wx * xsh[tx4 + 64 + 3] + bb);
        *(float4*)(orow + tx4 + 64) = o;
    }
}

// ---------------------------------------------------------------------------
// Step 0: h_{-1} = 0 so h_0[i, j] = tanh(Whx[i] * x[j, 0] + bh[i]). No GEMM.
// ---------------------------------------------------------------------------
__global__ void rnn_first(const float* __restrict__ xin,
                          const float* __restrict__ Whx,
                          const float* __restrict__ bh,
                          float* __restrict__ hout)
{
    const int j = blockIdx.x * blockDim.x + threadIdx.x;
    const int i = blockIdx.y;
    hout[(size_t)i * BD + j] = tanhf(Whx[i] * xin[(size_t)j * TD] + bh[i]);
}

// ---------------------------------------------------------------------------
// Output projection, split-K: part[ic][j][c] = sum_{i in chunk ic} Why[i,c]*h[i,j]
// ---------------------------------------------------------------------------
__global__ __launch_bounds__(256)
void rnn_out_partial(const float* __restrict__ h,
                     const float* __restrict__ Why,
                     float* __restrict__ part)
{
    __shared__ float sW[128][CD];
    const int tid = threadIdx.x;
    const int j  = blockIdx.x * 256 + tid;
    const int i0 = blockIdx.y * 128;

    for (int e = tid; e < 128 * CD; e += 256)
        sW[e / CD][e % CD] = Why[(size_t)(i0 + e / CD) * CD + (e % CD)];
    __syncthreads();

    float acc[CD];
#pragma unroll
    for (int c = 0; c < CD; ++c) acc[c] = 0.0f;

    for (int ii = 0; ii < 128; ++ii) {
        const float hv = h[(size_t)(i0 + ii) * BD + j];
#pragma unroll
        for (int c = 0; c < CD; ++c) acc[c] += hv * sW[ii][c];
    }

    float* p = part + ((size_t)blockIdx.y * BD + j) * CD;
#pragma unroll
    for (int c = 0; c < CD; ++c) p[c] = acc[c];
}

__global__ void rnn_out_reduce(const float* __restrict__ part,
                               const float* __restrict__ bp,
                               float* __restrict__ out)
{
    const int e = blockIdx.x * blockDim.x + threadIdx.x;
    if (e >= BD * CD) return;
    float s = bp[e % CD];
#pragma unroll
    for (int ic = 0; ic < 16; ++ic) s += part[(size_t)ic * BD * CD + e];
    out[e] = s;
}

// ---------------------------------------------------------------------------
extern "C" void kernel_launch(void* const* d_in, const int* in_sizes, int n_in,
                              void* d_out, int out_size)
{
    const float* x   = (const float*)d_in[0];
    const float* Whx = (const float*)d_in[1];
    const float* Whh = (const float*)d_in[2];
    const float* Why = (const float*)d_in[3];
    const float* bh  = (const float*)d_in[4];
    const float* bp  = (const float*)d_in[5];
    float* out = (float*)d_out;

    float* hbase = nullptr;
    cudaGetSymbolAddress((void**)&hbase, g_h);
    float* part = nullptr;
    cudaGetSymbolAddress((void**)&part, g_part);

    float* cur = hbase;                       // buffer 0
    float* nxt = hbase + (size_t)HD * BD;     // buffer 1

    rnn_first<<<dim3(BD / 256, HD), 256>>>(x, Whx, bh, cur);

    for (int t = 1; t < TD; ++t) {
        rnn_step<<<dim3(BD / BN, HD / BM), NTHREADS>>>(Whh, cur, Whx, x, bh, nxt, t);
        float* tmp = cur; cur = nxt; nxt = tmp;
    }

    rnn_out_partial<<<dim3(BD / 256, HD / 128), 256>>>(cur, Why, part);
    rnn_out_reduce<<<(BD * CD + 255) / 256, 256>>>(part, bp, out);
}

// round 8
// speedup vs baseline: 3.5095x; 3.5095x over previous
#include <cuda_runtime.h>
#include <cuda_bf16.h>
#include <cstdint>

// VanillaRNN: h_t = tanh(W_hh @ h_{t-1} + W_hx x_t + b_h); out = W_hy^T h_T + b_p
// H = B = 2048, T = 64, C = 10.
//
// GEMM orientation: C[n][m] = sum_k hT[n][k] * Whh[m][k]
//   A (m16 rows) = hT   [n][k]  row-major, K contiguous  -> a frag = 2 consecutive k
//   B (n8 cols)  = Whh  [m][k]  row-major, K contiguous  -> b frag = 2 consecutive k
//   C frag c0/c1 = adjacent m for one n -> direct bf16x2 stores in [n][m] layout,
//   which IS the next step's A layout. No transpose staging anywhere.
// 3-pass bf16 split (Hhi*Whi + Hhi*Wlo + Hlo*Whi), fp32 accum.

#define HD 2048
#define BD 2048
#define TD 64
#define CD 10

#define NC (HD / 32)       // 64 k-chunks of 32 elements

// smem layout (dynamic)
#define OFF_XS   0         // 128 floats: x[n0..n0+127][t]
#define OFF_WX   512       // 128 floats: Whx[m0..]
#define OFF_BH   1024      // 128 floats: bh[m0..]
#define OFF_T    2048      // tile buffers
#define PLANE    10240     // 128 rows * 80B padded
#define STAGE    40960     // Ahi|Alo|Bhi|Blo
#define A_HI     0
#define A_LO     10240
#define B_HI     20480
#define B_LO     30720
#define SMEM_TOTAL (OFF_T + 2 * STAGE)   // 83968

// Scratch planes (no allocation allowed)
__device__ __nv_bfloat16 g_Whi[(size_t)HD * HD];
__device__ __nv_bfloat16 g_Wlo[(size_t)HD * HD];
__device__ __nv_bfloat16 g_Hbuf[4][(size_t)BD * HD];   // [buf0 hi, buf0 lo, buf1 hi, buf1 lo]

// ---------------------------------------------------------------------------
__device__ __forceinline__ uint32_t smem_u32(const void* p) {
    uint32_t a;
    asm("{ .reg .u64 t; cvta.to.shared.u64 t, %1; cvt.u32.u64 %0, t; }" : "=r"(a) : "l"(p));
    return a;
}
__device__ __forceinline__ void cp16(uint32_t s, const void* g) {
    asm volatile("cp.async.cg.shared.global [%0], [%1], 16;" :: "r"(s), "l"(g));
}
__device__ __forceinline__ void cp_commit() {
    asm volatile("cp.async.commit_group;" ::: "memory");
}
__device__ __forceinline__ void cp_wait1() {
    asm volatile("cp.async.wait_group 1;" ::: "memory");
}
__device__ __forceinline__ void cp_wait0() {
    asm volatile("cp.async.wait_group 0;" ::: "memory");
}
__device__ __forceinline__ unsigned lds32(uint32_t a) {
    unsigned v;
    asm volatile("ld.shared.b32 %0, [%1];" : "=r"(v) : "r"(a));
    return v;
}
__device__ __forceinline__ void mma16816(float* c, const unsigned* a, const unsigned* b) {
    asm volatile("mma.sync.aligned.m16n8k16.row.col.f32.bf16.bf16.f32 "
                 "{%0,%1,%2,%3}, {%4,%5,%6,%7}, {%8,%9}, {%0,%1,%2,%3};"
                 : "+f"(c[0]), "+f"(c[1]), "+f"(c[2]), "+f"(c[3])
                 : "r"(a[0]), "r"(a[1]), "r"(a[2]), "r"(a[3]), "r"(b[0]), "r"(b[1]));
}

// MUFU-free tanh (pure FMA/ALU). Validated by hand at x = 0, +-0.5, 0.1, 3.
__device__ __forceinline__ float tanh_fast(float x) {
    float t = fminf(fabsf(x) * 2.885390081777927f, 60.0f);
    float r = t + 12582912.0f;
    int   ni = __float_as_int(r) - 0x4B400000;
    float f = t - (r - 12582912.0f);
    float p = 1.5403530394e-4f;
    p = fmaf(p, f, 1.3333558146e-3f);
    p = fmaf(p, f, 9.6181291076e-3f);
    p = fmaf(p, f, 5.5504108664e-2f);
    p = fmaf(p, f, 2.4022650696e-1f);
    p = fmaf(p, f, 6.9314718056e-1f);
    p = fmaf(p, f, 1.0f);
    float u = __int_as_float(__float_as_int(p) + (ni << 23));
    float d = u + 1.0f;
    float w = __int_as_float(0x7EF311C3 - __float_as_int(d));
    w = w * fmaf(-d, w, 2.0f);
    w = w * fmaf(-d, w, 2.0f);
    w = w * fmaf(-d, w, 2.0f);
    float y = fmaf(-2.0f, w, 1.0f);
    return __int_as_float(__float_as_int(y) | (__float_as_int(x) & 0x80000000));
}

// ---------------------------------------------------------------------------
// Prep kernels
// ---------------------------------------------------------------------------
__global__ void split_whh(const float* __restrict__ W,
                          __nv_bfloat16* __restrict__ Whi,
                          __nv_bfloat16* __restrict__ Wlo) {
    size_t e = (size_t)blockIdx.x * 256 + threadIdx.x;
    float v = W[e];
    __nv_bfloat16 hi = __float2bfloat16(v);
    Whi[e] = hi;
    Wlo[e] = __float2bfloat16(v - __bfloat162float(hi));
}

__global__ void rnn_first(const float* __restrict__ x, const float* __restrict__ Whx,
                          const float* __restrict__ bh,
                          __nv_bfloat16* __restrict__ Ohi, __nv_bfloat16* __restrict__ Olo) {
    int i = blockIdx.x * 256 + threadIdx.x;
    int n = blockIdx.y;
    float v = tanh_fast(fmaf(Whx[i], x[(size_t)n * TD], bh[i]));
    __nv_bfloat16 hi = __float2bfloat16(v);
    Ohi[(size_t)n * HD + i] = hi;
    Olo[(size_t)n * HD + i] = __float2bfloat16(v - __bfloat162float(hi));
}

// ---------------------------------------------------------------------------
// Main step. Grid (16 m-tiles, 16 n-tiles), 256 threads, 2 CTAs/SM.
// Fragment loads are direct LDS.32 per the PTX ISA mma.m16n8k16 tables:
//   gid = lane>>2, tig = lane&3
//   a0 = A[r=gid][k=2tig..]; a1 = A[r=gid+8][k]; a2 = A[r=gid][k+8]; a3 = A[r=gid+8][k+8]
//   b0 = B[k=2tig..][c=gid]; b1 = B[k+8][c=gid]
//   c0/c1 = C[r=gid][c=2tig, 2tig+1]; c2/c3 = row gid+8
// A rows = n (batch), B cols = m (hidden): both operands K-contiguous as stored.
// ---------------------------------------------------------------------------
extern __shared__ __align__(128) char smem[];

__global__ void __launch_bounds__(256, 2)
rnn_step(const __nv_bfloat16* __restrict__ Whi, const __nv_bfloat16* __restrict__ Wlo,
         const __nv_bfloat16* __restrict__ Hhi, const __nv_bfloat16* __restrict__ Hlo,
         __nv_bfloat16* __restrict__ Ohi, __nv_bfloat16* __restrict__ Olo,
         const float* __restrict__ x, const float* __restrict__ Whx,
         const float* __restrict__ bhv, int t)
{
    const uint32_t sb = smem_u32(smem);
    const int tid = threadIdx.x;
    const int wid = tid >> 5, l = tid & 31;
    const int m0 = blockIdx.x * 128;   // hidden (GEMM N dim)
    const int n0 = blockIdx.y * 128;   // batch  (GEMM M dim)

    if (tid < 128) {
        ((float*)(smem + OFF_XS))[tid] = x[(size_t)(n0 + tid) * TD + t];
        ((float*)(smem + OFF_WX))[tid] = Whx[m0 + tid];
        ((float*)(smem + OFF_BH))[tid] = bhv[m0 + tid];
    }

    // A tile <- h planes (rows n0+row); B tile <- W planes (rows m0+row)
#define ISSUE(c)                                                                   \
    do {                                                                           \
        const uint32_t _base = sb + OFF_T + ((c) & 1) * STAGE;                     \
        _Pragma("unroll")                                                          \
        for (int _i = 0; _i < 2; ++_i) {                                           \
            int _idx = tid + _i * 256;                                             \
            int _row = _idx >> 2, _q = _idx & 3;                                   \
            uint32_t _so = _row * 80 + _q * 16;                                    \
            size_t _ga = (size_t)(n0 + _row) * HD + (c) * 32 + _q * 8;             \
            size_t _gb = (size_t)(m0 + _row) * HD + (c) * 32 + _q * 8;             \
            cp16(_base + A_HI + _so, Hhi + _ga);                                   \
            cp16(_base + A_LO + _so, Hlo + _ga);                                   \
            cp16(_base + B_HI + _so, Whi + _gb);                                   \
            cp16(_base + B_LO + _so, Wlo + _gb);                                   \
        }                                                                          \
        cp_commit();                                                               \
    } while (0)

    ISSUE(0);
    ISSUE(1);

    float acc[2][8][4];
#pragma unroll
    for (int i = 0; i < 2; ++i)
#pragma unroll
        for (int j = 0; j < 8; ++j)
#pragma unroll
            for (int r = 0; r < 4; ++r) acc[i][j][r] = 0.0f;

    const int wn = (wid & 3) * 32;       // warp batch-row base (32 n rows)
    const int wm = (wid >> 2) * 64;      // warp hidden-col base (64 m cols)
    const int gid = l >> 2, tig = l & 3;

    const uint32_t aof = (uint32_t)(wn + gid) * 80 + tig * 4;   // h plane
    const uint32_t bof = (uint32_t)(wm + gid) * 80 + tig * 4;   // W plane

    for (int c = 0; c < NC; ++c) {
        if (c + 1 < NC) cp_wait1(); else cp_wait0();
        __syncthreads();
        const uint32_t base = sb + OFF_T + (c & 1) * STAGE;
        const uint32_t abase = base + A_HI + aof;
        const uint32_t bbase = base + B_HI + bof;

#pragma unroll
        for (int k16 = 0; k16 < 2; ++k16) {
            const uint32_t kb = k16 * 32;   // byte offset of this k16 block

            // A-hi fragments (h hi): sub = n subtile
            unsigned ah[2][4];
#pragma unroll
            for (int s = 0; s < 2; ++s) {
                uint32_t a0a = abase + s * (16 * 80) + kb;
                ah[s][0] = lds32(a0a);               // n gid,   k 0-7
                ah[s][1] = lds32(a0a + 640);         // n gid+8, k 0-7
                ah[s][2] = lds32(a0a + 16);          // n gid,   k 8-15
                ah[s][3] = lds32(a0a + 640 + 16);    // n gid+8, k 8-15
            }
            // B-hi fragments (W hi): g = m group of 16
            unsigned bw[4][4];
#pragma unroll
            for (int g = 0; g < 4; ++g) {
                uint32_t b0a = bbase + g * (16 * 80) + kb;
                bw[g][0] = lds32(b0a);                // m gid,   k 0-7   (b0)
                bw[g][1] = lds32(b0a + 16);           // m gid,   k 8-15  (b1)
                bw[g][2] = lds32(b0a + 640);          // m gid+8, k 0-7
                bw[g][3] = lds32(b0a + 640 + 16);     // m gid+8, k 8-15
            }
            // pass 1: Hhi * Whi
#pragma unroll
            for (int s = 0; s < 2; ++s)
#pragma unroll
                for (int g = 0; g < 4; ++g) {
                    mma16816(acc[s][2 * g],     ah[s], &bw[g][0]);
                    mma16816(acc[s][2 * g + 1], ah[s], &bw[g][2]);
                }
            // pass 2: Hhi * Wlo
            {
                unsigned bl[4][4];
#pragma unroll
                for (int g = 0; g < 4; ++g) {
                    uint32_t b0a = bbase + (B_LO - B_HI) + g * (16 * 80) + kb;
                    bl[g][0] = lds32(b0a);
                    bl[g][1] = lds32(b0a + 16);
                    bl[g][2] = lds32(b0a + 640);
                    bl[g][3] = lds32(b0a + 640 + 16);
                }
#pragma unroll
                for (int s = 0; s < 2; ++s)
#pragma unroll
                    for (int g = 0; g < 4; ++g) {
                        mma16816(acc[s][2 * g],     ah[s], &bl[g][0]);
                        mma16816(acc[s][2 * g + 1], ah[s], &bl[g][2]);
                    }
            }
            // pass 3: Hlo * Whi
            {
                unsigned al[2][4];
#pragma unroll
                for (int s = 0; s < 2; ++s) {
                    uint32_t a0a = abase + (A_LO - A_HI) + s * (16 * 80) + kb;
                    al[s][0] = lds32(a0a);
                    al[s][1] = lds32(a0a + 640);
                    al[s][2] = lds32(a0a + 16);
                    al[s][3] = lds32(a0a + 640 + 16);
                }
#pragma unroll
                for (int s = 0; s < 2; ++s)
#pragma unroll
                    for (int g = 0; g < 4; ++g) {
                        mma16816(acc[s][2 * g],     al[s], &bw[g][0]);
                        mma16816(acc[s][2 * g + 1], al[s], &bw[g][2]);
                    }
            }
        }
        __syncthreads();
        if (c + 2 < NC) ISSUE(c + 2);
    }
#undef ISSUE

    // ---- epilogue: z[n][m] = acc + wx[m]*x[n] + bh[m]; tanh; split; direct store ----
    // c0/c1 are adjacent m for row n=gid; c2/c3 same for n=gid+8 -> bf16x2 stores.
    {
        const float* xs  = (const float*)(smem + OFF_XS);
        const float* wxs = (const float*)(smem + OFF_WX);
        const float* bhs = (const float*)(smem + OFF_BH);
#pragma unroll
        for (int s = 0; s < 2; ++s) {
#pragma unroll
            for (int nt = 0; nt < 8; ++nt) {
                const int m = wm + nt * 8 + 2 * tig;          // even
                const float wx0 = wxs[m],     bb0 = bhs[m];
                const float wx1 = wxs[m + 1], bb1 = bhs[m + 1];
#pragma unroll
                for (int half = 0; half < 2; ++half) {
                    const int n = wn + s * 16 + gid + half * 8;
                    const float xn = xs[n];
                    float v0 = tanh_fast(acc[s][nt][2 * half + 0] + fmaf(wx0, xn, bb0));
                    float v1 = tanh_fast(acc[s][nt][2 * half + 1] + fmaf(wx1, xn, bb1));
                    __nv_bfloat162 ph, pl;
                    ph.x = __float2bfloat16(v0);
                    ph.y = __float2bfloat16(v1);
                    pl.x = __float2bfloat16(v0 - __bfloat162float(ph.x));
                    pl.y = __float2bfloat16(v1 - __bfloat162float(ph.y));
                    size_t gi = (size_t)(n0 + n) * HD + m0 + m;
                    *(__nv_bfloat162*)(Ohi + gi) = ph;
                    *(__nv_bfloat162*)(Olo + gi) = pl;
                }
            }
        }
    }
}

// ---------------------------------------------------------------------------
// Output projection: out[n][c] = sum_k (hi+lo)[n][k] * Why[k][c] + bp[c]
// ---------------------------------------------------------------------------
__global__ void __launch_bounds__(256)
rnn_out(const __nv_bfloat16* __restrict__ Hhi, const __nv_bfloat16* __restrict__ Hlo,
        const float* __restrict__ Why, const float* __restrict__ bp,
        float* __restrict__ out)
{
    const int wid = threadIdx.x >> 5, lane = threadIdx.x & 31;
    const int n = blockIdx.x * 8 + wid;
    float acc[CD];
#pragma unroll
    for (int c = 0; c < CD; ++c) acc[c] = 0.0f;

    for (int it = 0; it < 8; ++it) {
        int k0 = (it * 32 + lane) * 8;
        uint4 ph = *(const uint4*)&Hhi[(size_t)n * HD + k0];
        uint4 pl = *(const uint4*)&Hlo[(size_t)n * HD + k0];
        const unsigned rh[4] = {ph.x, ph.y, ph.z, ph.w};
        const unsigned rl[4] = {pl.x, pl.y, pl.z, pl.w};
#pragma unroll
        for (int kk = 0; kk < 4; ++kk) {
            __nv_bfloat162 h2 = *reinterpret_cast<const __nv_bfloat162*>(&rh[kk]);
            __nv_bfloat162 l2 = *reinterpret_cast<const __nv_bfloat162*>(&rl[kk]);
            float h0 = __bfloat162float(h2.x) + __bfloat162float(l2.x);
            float h1 = __bfloat162float(h2.y) + __bfloat162float(l2.y);
            const float* w0 = Why + (size_t)(k0 + 2 * kk) * CD;
            const float* w1 = w0 + CD;
#pragma unroll
            for (int c = 0; c < CD; ++c) {
                acc[c] = fmaf(h0, __ldg(w0 + c), acc[c]);
                acc[c] = fmaf(h1, __ldg(w1 + c), acc[c]);
            }
        }
    }
#pragma unroll
    for (int o = 16; o > 0; o >>= 1)
#pragma unroll
        for (int c = 0; c < CD; ++c)
            acc[c] += __shfl_xor_sync(0xFFFFFFFFu, acc[c], o);
    if (lane == 0) {
#pragma unroll
        for (int c = 0; c < CD; ++c) out[(size_t)n * CD + c] = acc[c] + bp[c];
    }
}

// ---------------------------------------------------------------------------
extern "C" void kernel_launch(void* const* d_in, const int* in_sizes, int n_in,
                              void* d_out, int out_size)
{
    const float* x   = (const float*)d_in[0];
    const float* Whx = (const float*)d_in[1];
    const float* Whh = (const float*)d_in[2];
    const float* Why = (const float*)d_in[3];
    const float* bh  = (const float*)d_in[4];
    const float* bp  = (const float*)d_in[5];
    float* out = (float*)d_out;

    cudaFuncSetAttribute(rnn_step, cudaFuncAttributeMaxDynamicSharedMemorySize, SMEM_TOTAL);

    __nv_bfloat16 *Whi = nullptr, *Wlo = nullptr, *Hb = nullptr;
    cudaGetSymbolAddress((void**)&Whi, g_Whi);
    cudaGetSymbolAddress((void**)&Wlo, g_Wlo);
    cudaGetSymbolAddress((void**)&Hb, g_Hbuf);
    const size_t S = (size_t)BD * HD;

    __nv_bfloat16* curHi = Hb;           // buf0
    __nv_bfloat16* curLo = Hb + S;
    __nv_bfloat16* nxtHi = Hb + 2 * S;   // buf1
    __nv_bfloat16* nxtLo = Hb + 3 * S;

    split_whh<<<(HD * HD) / 256, 256>>>(Whh, Whi, Wlo);
    rnn_first<<<dim3(HD / 256, BD), 256>>>(x, Whx, bh, curHi, curLo);

    for (int t = 1; t < TD; ++t) {
        rnn_step<<<dim3(16, 16), 256, SMEM_TOTAL>>>(Whi, Wlo, curHi, curLo,
                                                    nxtHi, nxtLo, x, Whx, bh, t);
        __nv_bfloat16* th = curHi; curHi = nxtHi; nxtHi = th;
        __nv_bfloat16* tl = curLo; curLo = nxtLo; nxtLo = tl;
    }

    rnn_out<<<BD / 8, 256>>>(curHi, curLo, Why, bp, out);
}

// round 9
// speedup vs baseline: 3.7551x; 1.0700x over previous
#include <cuda_runtime.h>
#include <cuda_bf16.h>
#include <cstdint>

// VanillaRNN: h_t = tanh(W_hh @ h_{t-1} + W_hx x_t + b_h); out = W_hy^T h_T + b_p
// H = B = 2048, T = 64, C = 10.
//
// GEMM orientation: C[n][m] = sum_k hT[n][k] * Whh[m][k]
//   A (m16 rows) = hT  [n][k] row-major, K contiguous
//   B (n8 cols)  = Whh [m][k] row-major, K contiguous
//   C frag c0/c1 = adjacent m for one n -> direct bf16x2 stores in [n][m] layout,
//   which IS the next step's A layout. No transpose staging anywhere.
// 3-pass bf16 split (Hhi*Whi + Hhi*Wlo + Hlo*Whi), fp32 accum.
// Fragments via ldmatrix.x4 (validated mapping; 4x fewer load instructions than LDS.32).

#define HD 2048
#define BD 2048
#define TD 64
#define CD 10

#define NC (HD / 32)       // 64 k-chunks of 32 elements

// smem layout (dynamic)
#define OFF_XS   0         // 128 floats: x[n0..n0+127][t]
#define OFF_WX   512       // 128 floats: Whx[m0..]
#define OFF_BH   1024      // 128 floats: bh[m0..]
#define OFF_T    2048      // tile buffers
#define PLANE    10240     // 128 rows * 80B padded
#define STAGE    40960     // Ahi|Alo|Bhi|Blo
#define A_HI     0
#define A_LO     10240
#define B_HI     20480
#define B_LO     30720
#define SMEM_TOTAL (OFF_T + 2 * STAGE)   // 83968

// Scratch planes (no allocation allowed)
__device__ __nv_bfloat16 g_Whi[(size_t)HD * HD];
__device__ __nv_bfloat16 g_Wlo[(size_t)HD * HD];
__device__ __nv_bfloat16 g_Hbuf[4][(size_t)BD * HD];   // [buf0 hi, buf0 lo, buf1 hi, buf1 lo]

// ---------------------------------------------------------------------------
__device__ __forceinline__ uint32_t smem_u32(const void* p) {
    uint32_t a;
    asm("{ .reg .u64 t; cvta.to.shared.u64 t, %1; cvt.u32.u64 %0, t; }" : "=r"(a) : "l"(p));
    return a;
}
__device__ __forceinline__ void cp16(uint32_t s, const void* g) {
    asm volatile("cp.async.cg.shared.global [%0], [%1], 16;" :: "r"(s), "l"(g));
}
__device__ __forceinline__ void cp_commit() {
    asm volatile("cp.async.commit_group;" ::: "memory");
}
__device__ __forceinline__ void cp_wait1() {
    asm volatile("cp.async.wait_group 1;" ::: "memory");
}
__device__ __forceinline__ void cp_wait0() {
    asm volatile("cp.async.wait_group 0;" ::: "memory");
}
__device__ __forceinline__ void ldsm4(unsigned* r, uint32_t a) {
    asm volatile("ldmatrix.sync.aligned.m8n8.x4.shared.b16 {%0,%1,%2,%3}, [%4];"
                 : "=r"(r[0]), "=r"(r[1]), "=r"(r[2]), "=r"(r[3]) : "r"(a));
}
__device__ __forceinline__ void mma16816(float* c, const unsigned* a, const unsigned* b) {
    asm volatile("mma.sync.aligned.m16n8k16.row.col.f32.bf16.bf16.f32 "
                 "{%0,%1,%2,%3}, {%4,%5,%6,%7}, {%8,%9}, {%0,%1,%2,%3};"
                 : "+f"(c[0]), "+f"(c[1]), "+f"(c[2]), "+f"(c[3])
                 : "r"(a[0]), "r"(a[1]), "r"(a[2]), "r"(a[3]), "r"(b[0]), "r"(b[1]));
}

// MUFU-free tanh (pure FMA/ALU).
__device__ __forceinline__ float tanh_fast(float x) {
    float t = fminf(fabsf(x) * 2.885390081777927f, 60.0f);
    float r = t + 12582912.0f;
    int   ni = __float_as_int(r) - 0x4B400000;
    float f = t - (r - 12582912.0f);
    float p = 1.5403530394e-4f;
    p = fmaf(p, f, 1.3333558146e-3f);
    p = fmaf(p, f, 9.6181291076e-3f);
    p = fmaf(p, f, 5.5504108664e-2f);
    p = fmaf(p, f, 2.4022650696e-1f);
    p = fmaf(p, f, 6.9314718056e-1f);
    p = fmaf(p, f, 1.0f);
    float u = __int_as_float(__float_as_int(p) + (ni << 23));
    float d = u + 1.0f;
    float w = __int_as_float(0x7EF311C3 - __float_as_int(d));
    w = w * fmaf(-d, w, 2.0f);
    w = w * fmaf(-d, w, 2.0f);
    w = w * fmaf(-d, w, 2.0f);
    float y = fmaf(-2.0f, w, 1.0f);
    return __int_as_float(__float_as_int(y) | (__float_as_int(x) & 0x80000000));
}

// ---------------------------------------------------------------------------
// Prep kernels
// ---------------------------------------------------------------------------
__global__ void split_whh(const float* __restrict__ W,
                          __nv_bfloat16* __restrict__ Whi,
                          __nv_bfloat16* __restrict__ Wlo) {
    size_t e = (size_t)blockIdx.x * 256 + threadIdx.x;
    float v = W[e];
    __nv_bfloat16 hi = __float2bfloat16(v);
    Whi[e] = hi;
    Wlo[e] = __float2bfloat16(v - __bfloat162float(hi));
}

__global__ void rnn_first(const float* __restrict__ x, const float* __restrict__ Whx,
                          const float* __restrict__ bh,
                          __nv_bfloat16* __restrict__ Ohi, __nv_bfloat16* __restrict__ Olo) {
    int i = blockIdx.x * 256 + threadIdx.x;
    int n = blockIdx.y;
    float v = tanh_fast(fmaf(Whx[i], x[(size_t)n * TD], bh[i]));
    __nv_bfloat16 hi = __float2bfloat16(v);
    Ohi[(size_t)n * HD + i] = hi;
    Olo[(size_t)n * HD + i] = __float2bfloat16(v - __bfloat162float(hi));
}

// ---------------------------------------------------------------------------
// Main step. Grid (16 m-tiles, 16 n-tiles), 256 threads, 2 CTAs/SM.
// ldmatrix.x4 lane->address maps (80B row pitch, conflict-free):
//   A 16x16: lanes 0-15 -> rows 0-15 bytes [kb,kb+16); lanes 16-31 -> rows 0-15 [kb+16,kb+32)
//     regs: r0=(row gid, k0-7) r1=(gid+8, k0-7) r2=(gid, k8-15) r3=(gid+8, k8-15)
//   B 16x16: lanes 0-7 -> m rows 0-7 [kb,+16); 8-15 -> m 0-7 [kb+16); 16-23 -> m 8-15 [kb);
//     24-31 -> m 8-15 [kb+16)  => regs r0,r1 = (b0,b1) for m gid; r2,r3 for m gid+8
// ---------------------------------------------------------------------------
extern __shared__ __align__(128) char smem[];

__global__ void __launch_bounds__(256, 2)
rnn_step(const __nv_bfloat16* __restrict__ Whi, const __nv_bfloat16* __restrict__ Wlo,
         const __nv_bfloat16* __restrict__ Hhi, const __nv_bfloat16* __restrict__ Hlo,
         __nv_bfloat16* __restrict__ Ohi, __nv_bfloat16* __restrict__ Olo,
         const float* __restrict__ x, const float* __restrict__ Whx,
         const float* __restrict__ bhv, int t)
{
    const uint32_t sb = smem_u32(smem);
    const int tid = threadIdx.x;
    const int wid = tid >> 5, l = tid & 31;
    const int m0 = blockIdx.x * 128;   // hidden (GEMM N dim)
    const int n0 = blockIdx.y * 128;   // batch  (GEMM M dim)

    if (tid < 128) {
        ((float*)(smem + OFF_XS))[tid] = x[(size_t)(n0 + tid) * TD + t];
        ((float*)(smem + OFF_WX))[tid] = Whx[m0 + tid];
        ((float*)(smem + OFF_BH))[tid] = bhv[m0 + tid];
    }

    // A tile <- h planes (rows n0+row); B tile <- W planes (rows m0+row)
#define ISSUE(c)                                                                   \
    do {                                                                           \
        const uint32_t _base = sb + OFF_T + ((c) & 1) * STAGE;                     \
        _Pragma("unroll")                                                          \
        for (int _i = 0; _i < 2; ++_i) {                                           \
            int _idx = tid + _i * 256;                                             \
            int _row = _idx >> 2, _q = _idx & 3;                                   \
            uint32_t _so = _row * 80 + _q * 16;                                    \
            size_t _ga = (size_t)(n0 + _row) * HD + (c) * 32 + _q * 8;             \
            size_t _gb = (size_t)(m0 + _row) * HD + (c) * 32 + _q * 8;             \
            cp16(_base + A_HI + _so, Hhi + _ga);                                   \
            cp16(_base + A_LO + _so, Hlo + _ga);                                   \
            cp16(_base + B_HI + _so, Whi + _gb);                                   \
            cp16(_base + B_LO + _so, Wlo + _gb);                                   \
        }                                                                          \
        cp_commit();                                                               \
    } while (0)

    ISSUE(0);
    ISSUE(1);

    float acc[2][8][4];
#pragma unroll
    for (int i = 0; i < 2; ++i)
#pragma unroll
        for (int j = 0; j < 8; ++j)
#pragma unroll
            for (int r = 0; r < 4; ++r) acc[i][j][r] = 0.0f;

    const int wn = (wid & 3) * 32;       // warp batch-row base (32 n rows)
    const int wm = (wid >> 2) * 64;      // warp hidden-col base (64 m cols)
    const int gid = l >> 2, tig = l & 3;

    // ldmatrix per-lane address offsets within a plane
    const uint32_t aof = (uint32_t)(wn + (l & 15)) * 80 + ((l >> 4) & 1) * 16;
    const uint32_t bof = (uint32_t)(wm + (l & 7) + ((l >> 4) & 1) * 8) * 80 + ((l >> 3) & 1) * 16;

    for (int c = 0; c < NC; ++c) {
        if (c + 1 < NC) cp_wait1(); else cp_wait0();
        __syncthreads();
        const uint32_t base = sb + OFF_T + (c & 1) * STAGE;
        const uint32_t abase = base + A_HI + aof;
        const uint32_t bbase = base + B_HI + bof;

#pragma unroll
        for (int k16 = 0; k16 < 2; ++k16) {
            const uint32_t kb = k16 * 32;   // byte offset of this k16 block

            // A-hi fragments (h hi): s = n subtile of 16
            unsigned ah[2][4];
#pragma unroll
            for (int s = 0; s < 2; ++s)
                ldsm4(ah[s], abase + s * (16 * 80) + kb);
            // B-hi fragments (W hi): g = m group of 16
            unsigned bw[4][4];
#pragma unroll
            for (int g = 0; g < 4; ++g)
                ldsm4(bw[g], bbase + g * (16 * 80) + kb);
            // pass 1: Hhi * Whi
#pragma unroll
            for (int s = 0; s < 2; ++s)
#pragma unroll
                for (int g = 0; g < 4; ++g) {
                    mma16816(acc[s][2 * g],     ah[s], &bw[g][0]);
                    mma16816(acc[s][2 * g + 1], ah[s], &bw[g][2]);
                }
            // pass 2: Hhi * Wlo
            {
                unsigned bl[4][4];
#pragma unroll
                for (int g = 0; g < 4; ++g)
                    ldsm4(bl[g], bbase + (B_LO - B_HI) + g * (16 * 80) + kb);
#pragma unroll
                for (int s = 0; s < 2; ++s)
#pragma unroll
                    for (int g = 0; g < 4; ++g) {
                        mma16816(acc[s][2 * g],     ah[s], &bl[g][0]);
                        mma16816(acc[s][2 * g + 1], ah[s], &bl[g][2]);
                    }
            }
            // pass 3: Hlo * Whi
            {
                unsigned al[2][4];
#pragma unroll
                for (int s = 0; s < 2; ++s)
                    ldsm4(al[s], abase + (A_LO - A_HI) + s * (16 * 80) + kb);
#pragma unroll
                for (int s = 0; s < 2; ++s)
#pragma unroll
                    for (int g = 0; g < 4; ++g) {
                        mma16816(acc[s][2 * g],     al[s], &bw[g][0]);
                        mma16816(acc[s][2 * g + 1], al[s], &bw[g][2]);
                    }
            }
        }
        __syncthreads();
        if (c + 2 < NC) ISSUE(c + 2);
    }
#undef ISSUE

    // ---- epilogue: z[n][m] = acc + wx[m]*x[n] + bh[m]; tanh; split; direct store ----
    {
        const float* xs  = (const float*)(smem + OFF_XS);
        const float* wxs = (const float*)(smem + OFF_WX);
        const float* bhs = (const float*)(smem + OFF_BH);
#pragma unroll
        for (int s = 0; s < 2; ++s) {
#pragma unroll
            for (int nt = 0; nt < 8; ++nt) {
                const int m = wm + nt * 8 + 2 * tig;          // even
                const float wx0 = wxs[m],     bb0 = bhs[m];
                const float wx1 = wxs[m + 1], bb1 = bhs[m + 1];
#pragma unroll
                for (int half = 0; half < 2; ++half) {
                    const int n = wn + s * 16 + gid + half * 8;
                    const float xn = xs[n];
                    float v0 = tanh_fast(acc[s][nt][2 * half + 0] + fmaf(wx0, xn, bb0));
                    float v1 = tanh_fast(acc[s][nt][2 * half + 1] + fmaf(wx1, xn, bb1));
                    __nv_bfloat162 ph, pl;
                    ph.x = __float2bfloat16(v0);
                    ph.y = __float2bfloat16(v1);
                    pl.x = __float2bfloat16(v0 - __bfloat162float(ph.x));
                    pl.y = __float2bfloat16(v1 - __bfloat162float(ph.y));
                    size_t gi = (size_t)(n0 + n) * HD + m0 + m;
                    *(__nv_bfloat162*)(Ohi + gi) = ph;
                    *(__nv_bfloat162*)(Olo + gi) = pl;
                }
            }
        }
    }
}

// ---------------------------------------------------------------------------
// Output projection: out[n][c] = sum_k (hi+lo)[n][k] * Why[k][c] + bp[c]
// ---------------------------------------------------------------------------
__global__ void __launch_bounds__(256)
rnn_out(const __nv_bfloat16* __restrict__ Hhi, const __nv_bfloat16* __restrict__ Hlo,
        const float* __restrict__ Why, const float* __restrict__ bp,
        float* __restrict__ out)
{
    const int wid = threadIdx.x >> 5, lane = threadIdx.x & 31;
    const int n = blockIdx.x * 8 + wid;
    float acc[CD];
#pragma unroll
    for (int c = 0; c < CD; ++c) acc[c] = 0.0f;

    for (int it = 0; it < 8; ++it) {
        int k0 = (it * 32 + lane) * 8;
        uint4 ph = *(const uint4*)&Hhi[(size_t)n * HD + k0];
        uint4 pl = *(const uint4*)&Hlo[(size_t)n * HD + k0];
        const unsigned rh[4] = {ph.x, ph.y, ph.z, ph.w};
        const unsigned rl[4] = {pl.x, pl.y, pl.z, pl.w};
#pragma unroll
        for (int kk = 0; kk < 4; ++kk) {
            __nv_bfloat162 h2 = *reinterpret_cast<const __nv_bfloat162*>(&rh[kk]);
            __nv_bfloat162 l2 = *reinterpret_cast<const __nv_bfloat162*>(&rl[kk]);
            float h0 = __bfloat162float(h2.x) + __bfloat162float(l2.x);
            float h1 = __bfloat162float(h2.y) + __bfloat162float(l2.y);
            const float* w0 = Why + (size_t)(k0 + 2 * kk) * CD;
            const float* w1 = w0 + CD;
#pragma unroll
            for (int c = 0; c < CD; ++c) {
                acc[c] = fmaf(h0, __ldg(w0 + c), acc[c]);
                acc[c] = fmaf(h1, __ldg(w1 + c), acc[c]);
            }
        }
    }
#pragma unroll
    for (int o = 16; o > 0; o >>= 1)
#pragma unroll
        for (int c = 0; c < CD; ++c)
            acc[c] += __shfl_xor_sync(0xFFFFFFFFu, acc[c], o);
    if (lane == 0) {
#pragma unroll
        for (int c = 0; c < CD; ++c) out[(size_t)n * CD + c] = acc[c] + bp[c];
    }
}

// ---------------------------------------------------------------------------
extern "C" void kernel_launch(void* const* d_in, const int* in_sizes, int n_in,
                              void* d_out, int out_size)
{
    const float* x   = (const float*)d_in[0];
    const float* Whx = (const float*)d_in[1];
    const float* Whh = (const float*)d_in[2];
    const float* Why = (const float*)d_in[3];
    const float* bh  = (const float*)d_in[4];
    const float* bp  = (const float*)d_in[5];
    float* out = (float*)d_out;

    cudaFuncSetAttribute(rnn_step, cudaFuncAttributeMaxDynamicSharedMemorySize, SMEM_TOTAL);

    __nv_bfloat16 *Whi = nullptr, *Wlo = nullptr, *Hb = nullptr;
    cudaGetSymbolAddress((void**)&Whi, g_Whi);
    cudaGetSymbolAddress((void**)&Wlo, g_Wlo);
    cudaGetSymbolAddress((void**)&Hb, g_Hbuf);
    const size_t S = (size_t)BD * HD;

    __nv_bfloat16* curHi = Hb;           // buf0
    __nv_bfloat16* curLo = Hb + S;
    __nv_bfloat16* nxtHi = Hb + 2 * S;   // buf1
    __nv_bfloat16* nxtLo = Hb + 3 * S;

    split_whh<<<(HD * HD) / 256, 256>>>(Whh, Whi, Wlo);
    rnn_first<<<dim3(HD / 256, BD), 256>>>(x, Whx, bh, curHi, curLo);

    for (int t = 1; t < TD; ++t) {
        rnn_step<<<dim3(16, 16), 256, SMEM_TOTAL>>>(Whi, Wlo, curHi, curLo,
                                                    nxtHi, nxtLo, x, Whx, bh, t);
        __nv_bfloat16* th = curHi; curHi = nxtHi; nxtHi = th;
        __nv_bfloat16* tl = curLo; curLo = nxtLo; nxtLo = tl;
    }

    rnn_out<<<BD / 8, 256>>>(curHi, curLo, Why, bp, out);
}

// round 11
// speedup vs baseline: 3.8612x; 1.0283x over previous
#include <cuda_runtime.h>
#include <cuda_bf16.h>
#include <cstdint>

// VanillaRNN: h_t = tanh(W_hh @ h_{t-1} + W_hx x_t + b_h); out = W_hy^T h_T + b_p
// H = B = 2048, T = 64, C = 10.
//
// GEMM orientation: C[n][m] = sum_k hT[n][k] * Whh[m][k]; output fragment layout
// [n][m] == next step's A operand layout (no transpose staging).
// 3-pass bf16 split (Hhi*Whi + Hhi*Wlo + Hlo*Whi), fp32 accum, mma.m16n8k16.
// 3-stage cp.async pipeline, ONE __syncthreads per chunk, pitch-64 XOR-16 swizzle.

#define HD 2048
#define BD 2048
#define TD 64
#define CD 10

#define NC (HD / 32)       // 64 k-chunks of 32 elements

// smem layout (dynamic)
#define OFF_XS   0         // 128 floats: x[n0..n0+127][t]
#define OFF_WX   512       // 128 floats: Whx[m0..]
#define OFF_BH   1024      // 128 floats: bh[m0..]
#define OFF_T    2048      // tile buffers
#define PLANE    8192      // 128 rows * 64B (XOR-swizzled chunks)
#define STAGE    32768     // Ahi|Alo|Bhi|Blo
#define A_HI     0
#define A_LO     8192
#define B_HI     16384
#define B_LO     24576
#define NSTAGE   3
#define SMEM_TOTAL (OFF_T + NSTAGE * STAGE)   // 100352

// Scratch planes (no allocation allowed)
__device__ __nv_bfloat16 g_Whi[(size_t)HD * HD];
__device__ __nv_bfloat16 g_Wlo[(size_t)HD * HD];
__device__ __nv_bfloat16 g_Hbuf[4][(size_t)BD * HD];   // [buf0 hi, buf0 lo, buf1 hi, buf1 lo]

// ---------------------------------------------------------------------------
__device__ __forceinline__ uint32_t smem_u32(const void* p) {
    uint32_t a;
    asm("{ .reg .u64 t; cvta.to.shared.u64 t, %1; cvt.u32.u64 %0, t; }" : "=r"(a) : "l"(p));
    return a;
}
__device__ __forceinline__ void cp16(uint32_t s, const void* g) {
    asm volatile("cp.async.cg.shared.global [%0], [%1], 16;" :: "r"(s), "l"(g));
}
__device__ __forceinline__ void cp_commit() {
    asm volatile("cp.async.commit_group;" ::: "memory");
}
__device__ __forceinline__ void cp_wait1() {
    asm volatile("cp.async.wait_group 1;" ::: "memory");
}
__device__ __forceinline__ void cp_wait0() {
    asm volatile("cp.async.wait_group 0;" ::: "memory");
}
__device__ __forceinline__ void ldsm4(unsigned* r, uint32_t a) {
    asm volatile("ldmatrix.sync.aligned.m8n8.x4.shared.b16 {%0,%1,%2,%3}, [%4];"
                 : "=r"(r[0]), "=r"(r[1]), "=r"(r[2]), "=r"(r[3]) : "r"(a));
}
__device__ __forceinline__ void mma16816(float* c, const unsigned* a, const unsigned* b) {
    asm volatile("mma.sync.aligned.m16n8k16.row.col.f32.bf16.bf16.f32 "
                 "{%0,%1,%2,%3}, {%4,%5,%6,%7}, {%8,%9}, {%0,%1,%2,%3};"
                 : "+f"(c[0]), "+f"(c[1]), "+f"(c[2]), "+f"(c[3])
                 : "r"(a[0]), "r"(a[1]), "r"(a[2]), "r"(a[3]), "r"(b[0]), "r"(b[1]));
}

// MUFU-free tanh (pure FMA/ALU).
__device__ __forceinline__ float tanh_fast(float x) {
    float t = fminf(fabsf(x) * 2.885390081777927f, 60.0f);
    float r = t + 12582912.0f;
    int   ni = __float_as_int(r) - 0x4B400000;
    float f = t - (r - 12582912.0f);
    float p = 1.5403530394e-4f;
    p = fmaf(p, f, 1.3333558146e-3f);
    p = fmaf(p, f, 9.6181291076e-3f);
    p = fmaf(p, f, 5.5504108664e-2f);
    p = fmaf(p, f, 2.4022650696e-1f);
    p = fmaf(p, f, 6.9314718056e-1f);
    p = fmaf(p, f, 1.0f);
    float u = __int_as_float(__float_as_int(p) + (ni << 23));
    float d = u + 1.0f;
    float w = __int_as_float(0x7EF311C3 - __float_as_int(d));
    w = w * fmaf(-d, w, 2.0f);
    w = w * fmaf(-d, w, 2.0f);
    w = w * fmaf(-d, w, 2.0f);
    float y = fmaf(-2.0f, w, 1.0f);
    return __int_as_float(__float_as_int(y) | (__float_as_int(x) & 0x80000000));
}

// ---------------------------------------------------------------------------
// Prep kernels
// ---------------------------------------------------------------------------
__global__ void split_whh(const float* __restrict__ W,
                          __nv_bfloat16* __restrict__ Whi,
                          __nv_bfloat16* __restrict__ Wlo) {
    size_t e = (size_t)blockIdx.x * 256 + threadIdx.x;
    float v = W[e];
    __nv_bfloat16 hi = __float2bfloat16(v);
    Whi[e] = hi;
    Wlo[e] = __float2bfloat16(v - __bfloat162float(hi));
}

__global__ void rnn_first(const float* __restrict__ x, const float* __restrict__ Whx,
                          const float* __restrict__ bh,
                          __nv_bfloat16* __restrict__ Ohi, __nv_bfloat16* __restrict__ Olo) {
    int i = blockIdx.x * 256 + threadIdx.x;
    int n = blockIdx.y;
    float v = tanh_fast(fmaf(Whx[i], x[(size_t)n * TD], bh[i]));
    __nv_bfloat16 hi = __float2bfloat16(v);
    Ohi[(size_t)n * HD + i] = hi;
    Olo[(size_t)n * HD + i] = __float2bfloat16(v - __bfloat162float(hi));
}

// ---------------------------------------------------------------------------
// Main step. Grid (16 m-tiles, 16 n-tiles), 256 threads, 2 CTAs/SM.
// Swizzle: element 16B-chunk q of row r stored at r*64 + (q ^ (r&3))*16.
// 3-stage pipeline: at iter c, wait for chunk c, sync once, issue chunk c+2
// into buffer (c+2)%3 (freed by the sync), then compute chunk c.
// ---------------------------------------------------------------------------
extern __shared__ __align__(128) char smem[];

__global__ void __launch_bounds__(256, 2)
rnn_step(const __nv_bfloat16* __restrict__ Whi, const __nv_bfloat16* __restrict__ Wlo,
         const __nv_bfloat16* __restrict__ Hhi, const __nv_bfloat16* __restrict__ Hlo,
         __nv_bfloat16* __restrict__ Ohi, __nv_bfloat16* __restrict__ Olo,
         const float* __restrict__ x, const float* __restrict__ Whx,
         const float* __restrict__ bhv, int t)
{
    const uint32_t sb = smem_u32(smem);
    const int tid = threadIdx.x;
    const int wid = tid >> 5, l = tid & 31;
    const int m0 = blockIdx.x * 128;   // hidden (GEMM N dim)
    const int n0 = blockIdx.y * 128;   // batch  (GEMM M dim)

    if (tid < 128) {
        ((float*)(smem + OFF_XS))[tid] = x[(size_t)(n0 + tid) * TD + t];
        ((float*)(smem + OFF_WX))[tid] = Whx[m0 + tid];
        ((float*)(smem + OFF_BH))[tid] = bhv[m0 + tid];
    }

    // A tile <- h planes (rows n0+row); B tile <- W planes (rows m0+row)
#define ISSUE(c)                                                                   \
    do {                                                                           \
        const uint32_t _base = sb + OFF_T + ((c) % NSTAGE) * STAGE;                \
        _Pragma("unroll")                                                          \
        for (int _i = 0; _i < 2; ++_i) {                                           \
            int _idx = tid + _i * 256;                                             \
            int _row = _idx >> 2, _q = _idx & 3;                                   \
            uint32_t _so = _row * 64 + ((_q ^ (_row & 3)) << 4);                   \
            size_t _ga = (size_t)(n0 + _row) * HD + (c) * 32 + _q * 8;             \
            size_t _gb = (size_t)(m0 + _row) * HD + (c) * 32 + _q * 8;             \
            cp16(_base + A_HI + _so, Hhi + _ga);                                   \
            cp16(_base + A_LO + _so, Hlo + _ga);                                   \
            cp16(_base + B_HI + _so, Whi + _gb);                                   \
            cp16(_base + B_LO + _so, Wlo + _gb);                                   \
        }                                                                          \
        cp_commit();                                                               \
    } while (0)

    ISSUE(0);
    ISSUE(1);

    float acc[2][8][4];
#pragma unroll
    for (int i = 0; i < 2; ++i)
#pragma unroll
        for (int j = 0; j < 8; ++j)
#pragma unroll
            for (int r = 0; r < 4; ++r) acc[i][j][r] = 0.0f;

    const int wn = (wid & 3) * 32;       // warp batch-row base (32 n rows)
    const int wm = (wid >> 2) * 64;      // warp hidden-col base (64 m cols)
    const int gid = l >> 2, tig = l & 3;

    // ldmatrix per-lane logical (row, chunk) -> swizzled byte offsets
    const int r3 = l & 3;
    const uint32_t abase = (uint32_t)(wn + (l & 15)) * 64;                        // + s*1024
    const uint32_t bbase = (uint32_t)(wm + (l & 7) + ((l >> 4) & 1) * 8) * 64;    // + g*1024
    const int qa = (l >> 4) & 1;
    const int qb = (l >> 3) & 1;
    const uint32_t aswz[2] = { (uint32_t)((qa ^ r3) << 4), (uint32_t)(((qa + 2) ^ r3) << 4) };
    const uint32_t bswz[2] = { (uint32_t)((qb ^ r3) << 4), (uint32_t)(((qb + 2) ^ r3) << 4) };

    for (int c = 0; c < NC; ++c) {
        if (c + 1 < NC) cp_wait1(); else cp_wait0();
        __syncthreads();
        if (c + 2 < NC) ISSUE(c + 2);   // buffer (c+2)%3 freed by the sync above

        const uint32_t stg = sb + OFF_T + (c % NSTAGE) * STAGE;
        const uint32_t astg = stg + A_HI + abase;
        const uint32_t bstg = stg + B_HI + bbase;

#pragma unroll
        for (int k16 = 0; k16 < 2; ++k16) {
            // A-hi fragments (h hi): s = n subtile of 16
            unsigned ah[2][4];
#pragma unroll
            for (int s = 0; s < 2; ++s)
                ldsm4(ah[s], astg + s * 1024 + aswz[k16]);
            // B-hi fragments (W hi): g = m group of 16
            unsigned bw[4][4];
#pragma unroll
            for (int g = 0; g < 4; ++g)
                ldsm4(bw[g], bstg + g * 1024 + bswz[k16]);
            // pass 1: Hhi * Whi
#pragma unroll
            for (int s = 0; s < 2; ++s)
#pragma unroll
                for (int g = 0; g < 4; ++g) {
                    mma16816(acc[s][2 * g],     ah[s], &bw[g][0]);
                    mma16816(acc[s][2 * g + 1], ah[s], &bw[g][2]);
                }
            // pass 2: Hhi * Wlo
            {
                unsigned bl[4][4];
#pragma unroll
                for (int g = 0; g < 4; ++g)
                    ldsm4(bl[g], bstg + (B_LO - B_HI) + g * 1024 + bswz[k16]);
#pragma unroll
                for (int s = 0; s < 2; ++s)
#pragma unroll
                    for (int g = 0; g < 4; ++g) {
                        mma16816(acc[s][2 * g],     ah[s], &bl[g][0]);
                        mma16816(acc[s][2 * g + 1], ah[s], &bl[g][2]);
                    }
            }
            // pass 3: Hlo * Whi
            {
                unsigned al[2][4];
#pragma unroll
                for (int s = 0; s < 2; ++s)
                    ldsm4(al[s], astg + (A_LO - A_HI) + s * 1024 + aswz[k16]);
#pragma unroll
                for (int s = 0; s < 2; ++s)
#pragma unroll
                    for (int g = 0; g < 4; ++g) {
                        mma16816(acc[s][2 * g],     al[s], &bw[g][0]);
                        mma16816(acc[s][2 * g + 1], al[s], &bw[g][2]);
                    }
            }
        }
    }
#undef ISSUE

    // ---- epilogue: z[n][m] = acc + wx[m]*x[n] + bh[m]; tanh; split; direct store ----
    {
        const float* xs  = (const float*)(smem + OFF_XS);
        const float* wxs = (const float*)(smem + OFF_WX);
        const float* bhs = (const float*)(smem + OFF_BH);
#pragma unroll
        for (int s = 0; s < 2; ++s) {
#pragma unroll
            for (int nt = 0; nt < 8; ++nt) {
                const int m = wm + nt * 8 + 2 * tig;          // even
                const float wx0 = wxs[m],     bb0 = bhs[m];
                const float wx1 = wxs[m + 1], bb1 = bhs[m + 1];
#pragma unroll
                for (int half = 0; half < 2; ++half) {
                    const int n = wn + s * 16 + gid + half * 8;
                    const float xn = xs[n];
                    float v0 = tanh_fast(acc[s][nt][2 * half + 0] + fmaf(wx0, xn, bb0));
                    float v1 = tanh_fast(acc[s][nt][2 * half + 1] + fmaf(wx1, xn, bb1));
                    __nv_bfloat162 ph, pl;
                    ph.x = __float2bfloat16(v0);
                    ph.y = __float2bfloat16(v1);
                    pl.x = __float2bfloat16(v0 - __bfloat162float(ph.x));
                    pl.y = __float2bfloat16(v1 - __bfloat162float(ph.y));
                    size_t gi = (size_t)(n0 + n) * HD + m0 + m;
                    *(__nv_bfloat162*)(Ohi + gi) = ph;
                    *(__nv_bfloat162*)(Olo + gi) = pl;
                }
            }
        }
    }
}

// ---------------------------------------------------------------------------
// Output projection: out[n][c] = sum_k (hi+lo)[n][k] * Why[k][c] + bp[c]
// ---------------------------------------------------------------------------
__global__ void __launch_bounds__(256)
rnn_out(const __nv_bfloat16* __restrict__ Hhi, const __nv_bfloat16* __restrict__ Hlo,
        const float* __restrict__ Why, const float* __restrict__ bp,
        float* __restrict__ out)
{
    const int wid = threadIdx.x >> 5, lane = threadIdx.x & 31;
    const int n = blockIdx.x * 8 + wid;
    float acc[CD];
#pragma unroll
    for (int c = 0; c < CD; ++c) acc[c] = 0.0f;

    for (int it = 0; it < 8; ++it) {
        int k0 = (it * 32 + lane) * 8;
        uint4 ph = *(const uint4*)&Hhi[(size_t)n * HD + k0];
        uint4 pl = *(const uint4*)&Hlo[(size_t)n * HD + k0];
        const unsigned rh[4] = {ph.x, ph.y, ph.z, ph.w};
        const unsigned rl[4] = {pl.x, pl.y, pl.z, pl.w};
#pragma unroll
        for (int kk = 0; kk < 4; ++kk) {
            __nv_bfloat162 h2 = *reinterpret_cast<const __nv_bfloat162*>(&rh[kk]);
            __nv_bfloat162 l2 = *reinterpret_cast<const __nv_bfloat162*>(&rl[kk]);
            float h0 = __bfloat162float(h2.x) + __bfloat162float(l2.x);
            float h1 = __bfloat162float(h2.y) + __bfloat162float(l2.y);
            const float* w0 = Why + (size_t)(k0 + 2 * kk) * CD;
            const float* w1 = w0 + CD;
#pragma unroll
            for (int c = 0; c < CD; ++c) {
                acc[c] = fmaf(h0, __ldg(w0 + c), acc[c]);
                acc[c] = fmaf(h1, __ldg(w1 + c), acc[c]);
            }
        }
    }
#pragma unroll
    for (int o = 16; o > 0; o >>= 1)
#pragma unroll
        for (int c = 0; c < CD; ++c)
            acc[c] += __shfl_xor_sync(0xFFFFFFFFu, acc[c], o);
    if (lane == 0) {
#pragma unroll
        for (int c = 0; c < CD; ++c) out[(size_t)n * CD + c] = acc[c] + bp[c];
    }
}

// ---------------------------------------------------------------------------
extern "C" void kernel_launch(void* const* d_in, const int* in_sizes, int n_in,
                              void* d_out, int out_size)
{
    const float* x   = (const float*)d_in[0];
    const float* Whx = (const float*)d_in[1];
    const float* Whh = (const float*)d_in[2];
    const float* Why = (const float*)d_in[3];
    const float* bh  = (const float*)d_in[4];
    const float* bp  = (const float*)d_in[5];
    float* out = (float*)d_out;

    cudaFuncSetAttribute(rnn_step, cudaFuncAttributeMaxDynamicSharedMemorySize, SMEM_TOTAL);

    __nv_bfloat16 *Whi = nullptr, *Wlo = nullptr, *Hb = nullptr;
    cudaGetSymbolAddress((void**)&Whi, g_Whi);
    cudaGetSymbolAddress((void**)&Wlo, g_Wlo);
    cudaGetSymbolAddress((void**)&Hb, g_Hbuf);
    const size_t S = (size_t)BD * HD;

    __nv_bfloat16* curHi = Hb;           // buf0
    __nv_bfloat16* curLo = Hb + S;
    __nv_bfloat16* nxtHi = Hb + 2 * S;   // buf1
    __nv_bfloat16* nxtLo = Hb + 3 * S;

    split_whh<<<(HD * HD) / 256, 256>>>(Whh, Whi, Wlo);
    rnn_first<<<dim3(HD / 256, BD), 256>>>(x, Whx, bh, curHi, curLo);

    for (int t = 1; t < TD; ++t) {
        rnn_step<<<dim3(16, 16), 256, SMEM_TOTAL>>>(Whi, Wlo, curHi, curLo,
                                                    nxtHi, nxtLo, x, Whx, bh, t);
        __nv_bfloat16* th = curHi; curHi = nxtHi; nxtHi = th;
        __nv_bfloat16* tl = curLo; curLo = nxtLo; nxtLo = tl;
    }

    rnn_out<<<BD / 8, 256>>>(curHi, curLo, Why, bp, out);
}

// round 16
// speedup vs baseline: 4.0184x; 1.0407x over previous
#include <cuda_runtime.h>
#include <cuda_bf16.h>
#include <cstdint>

// VanillaRNN: h_t = tanh(W_hh @ h_{t-1} + W_hx x_t + b_h); out = W_hy^T h_T + b_p
// H = B = 2048, T = 64, C = 10.
//
// GEMM orientation: C[n][m] = sum_k hT[n][k] * Whh[m][k]; output fragment layout
// [n][m] == next step's A operand layout (no transpose staging).
// 3-pass bf16 split (Hhi*Whi + Hhi*Wlo + Hlo*Whi), fp32 accum, mma.m16n8k16.
// 3-stage cp.async pipeline, ONE __syncthreads per chunk, pitch-64 XOR-16 swizzle.
// Mainloop: per-g software pipeline — W fragments (hi+lo) for group g+1 are
// prefetched BEFORE group g's 12 mma, so ldsm latency hides under mma issue.

#define HD 2048
#define BD 2048
#define TD 64
#define CD 10

#define NC (HD / 32)       // 64 k-chunks of 32 elements

// smem layout (dynamic)
#define OFF_XS   0         // 128 floats: x[n0..n0+127][t]
#define OFF_WX   512       // 128 floats: Whx[m0..]
#define OFF_BH   1024      // 128 floats: bh[m0..]
#define OFF_T    2048      // tile buffers
#define PLANE    8192      // 128 rows * 64B (XOR-swizzled chunks)
#define STAGE    32768     // Ahi|Alo|Bhi|Blo
#define A_HI     0
#define A_LO     8192
#define B_HI     16384
#define B_LO     24576
#define NSTAGE   3
#define SMEM_TOTAL (OFF_T + NSTAGE * STAGE)   // 100352

// Scratch planes (no allocation allowed)
__device__ __nv_bfloat16 g_Whi[(size_t)HD * HD];
__device__ __nv_bfloat16 g_Wlo[(size_t)HD * HD];
__device__ __nv_bfloat16 g_Hbuf[4][(size_t)BD * HD];   // [buf0 hi, buf0 lo, buf1 hi, buf1 lo]

// ---------------------------------------------------------------------------
__device__ __forceinline__ uint32_t smem_u32(const void* p) {
    uint32_t a;
    asm("{ .reg .u64 t; cvta.to.shared.u64 t, %1; cvt.u32.u64 %0, t; }" : "=r"(a) : "l"(p));
    return a;
}
__device__ __forceinline__ void cp16(uint32_t s, const void* g) {
    asm volatile("cp.async.cg.shared.global [%0], [%1], 16;" :: "r"(s), "l"(g));
}
__device__ __forceinline__ void cp_commit() {
    asm volatile("cp.async.commit_group;" ::: "memory");
}
__device__ __forceinline__ void cp_wait1() {
    asm volatile("cp.async.wait_group 1;" ::: "memory");
}
__device__ __forceinline__ void cp_wait0() {
    asm volatile("cp.async.wait_group 0;" ::: "memory");
}
__device__ __forceinline__ void ldsm4(unsigned* r, uint32_t a) {
    asm volatile("ldmatrix.sync.aligned.m8n8.x4.shared.b16 {%0,%1,%2,%3}, [%4];"
                 : "=r"(r[0]), "=r"(r[1]), "=r"(r[2]), "=r"(r[3]) : "r"(a));
}
__device__ __forceinline__ void mma16816(float* c, const unsigned* a, const unsigned* b) {
    asm volatile("mma.sync.aligned.m16n8k16.row.col.f32.bf16.bf16.f32 "
                 "{%0,%1,%2,%3}, {%4,%5,%6,%7}, {%8,%9}, {%0,%1,%2,%3};"
                 : "+f"(c[0]), "+f"(c[1]), "+f"(c[2]), "+f"(c[3])
                 : "r"(a[0]), "r"(a[1]), "r"(a[2]), "r"(a[3]), "r"(b[0]), "r"(b[1]));
}

// MUFU-free tanh (pure FMA/ALU).
__device__ __forceinline__ float tanh_fast(float x) {
    float t = fminf(fabsf(x) * 2.885390081777927f, 60.0f);
    float r = t + 12582912.0f;
    int   ni = __float_as_int(r) - 0x4B400000;
    float f = t - (r - 12582912.0f);
    float p = 1.5403530394e-4f;
    p = fmaf(p, f, 1.3333558146e-3f);
    p = fmaf(p, f, 9.6181291076e-3f);
    p = fmaf(p, f, 5.5504108664e-2f);
    p = fmaf(p, f, 2.4022650696e-1f);
    p = fmaf(p, f, 6.9314718056e-1f);
    p = fmaf(p, f, 1.0f);
    float u = __int_as_float(__float_as_int(p) + (ni << 23));
    float d = u + 1.0f;
    float w = __int_as_float(0x7EF311C3 - __float_as_int(d));
    w = w * fmaf(-d, w, 2.0f);
    w = w * fmaf(-d, w, 2.0f);
    w = w * fmaf(-d, w, 2.0f);
    float y = fmaf(-2.0f, w, 1.0f);
    return __int_as_float(__float_as_int(y) | (__float_as_int(x) & 0x80000000));
}

// ---------------------------------------------------------------------------
// Prep kernels
// ---------------------------------------------------------------------------
__global__ void split_whh(const float* __restrict__ W,
                          __nv_bfloat16* __restrict__ Whi,
                          __nv_bfloat16* __restrict__ Wlo) {
    size_t e = (size_t)blockIdx.x * 256 + threadIdx.x;
    float v = W[e];
    __nv_bfloat16 hi = __float2bfloat16(v);
    Whi[e] = hi;
    Wlo[e] = __float2bfloat16(v - __bfloat162float(hi));
}

__global__ void rnn_first(const float* __restrict__ x, const float* __restrict__ Whx,
                          const float* __restrict__ bh,
                          __nv_bfloat16* __restrict__ Ohi, __nv_bfloat16* __restrict__ Olo) {
    int i = blockIdx.x * 256 + threadIdx.x;
    int n = blockIdx.y;
    float v = tanh_fast(fmaf(Whx[i], x[(size_t)n * TD], bh[i]));
    __nv_bfloat16 hi = __float2bfloat16(v);
    Ohi[(size_t)n * HD + i] = hi;
    Olo[(size_t)n * HD + i] = __float2bfloat16(v - __bfloat162float(hi));
}

// ---------------------------------------------------------------------------
// Main step. Grid (16 m-tiles, 16 n-tiles), 256 threads, 2 CTAs/SM.
// Swizzle: element 16B-chunk q of row r stored at r*64 + (q ^ (r&3))*16.
// ---------------------------------------------------------------------------
extern __shared__ __align__(128) char smem[];

__global__ void __launch_bounds__(256, 2)
rnn_step(const __nv_bfloat16* __restrict__ Whi, const __nv_bfloat16* __restrict__ Wlo,
         const __nv_bfloat16* __restrict__ Hhi, const __nv_bfloat16* __restrict__ Hlo,
         __nv_bfloat16* __restrict__ Ohi, __nv_bfloat16* __restrict__ Olo,
         const float* __restrict__ x, const float* __restrict__ Whx,
         const float* __restrict__ bhv, int t)
{
    const uint32_t sb = smem_u32(smem);
    const int tid = threadIdx.x;
    const int wid = tid >> 5, l = tid & 31;
    const int m0 = blockIdx.x * 128;   // hidden (GEMM N dim)
    const int n0 = blockIdx.y * 128;   // batch  (GEMM M dim)

    if (tid < 128) {
        ((float*)(smem + OFF_XS))[tid] = x[(size_t)(n0 + tid) * TD + t];
        ((float*)(smem + OFF_WX))[tid] = Whx[m0 + tid];
        ((float*)(smem + OFF_BH))[tid] = bhv[m0 + tid];
    }

    // A tile <- h planes (rows n0+row); B tile <- W planes (rows m0+row)
#define ISSUE(c)                                                                   \
    do {                                                                           \
        const uint32_t _base = sb + OFF_T + ((c) % NSTAGE) * STAGE;                \
        _Pragma("unroll")                                                          \
        for (int _i = 0; _i < 2; ++_i) {                                           \
            int _idx = tid + _i * 256;                                             \
            int _row = _idx >> 2, _q = _idx & 3;                                   \
            uint32_t _so = _row * 64 + ((_q ^ (_row & 3)) << 4);                   \
            size_t _ga = (size_t)(n0 + _row) * HD + (c) * 32 + _q * 8;             \
            size_t _gb = (size_t)(m0 + _row) * HD + (c) * 32 + _q * 8;             \
            cp16(_base + A_HI + _so, Hhi + _ga);                                   \
            cp16(_base + A_LO + _so, Hlo + _ga);                                   \
            cp16(_base + B_HI + _so, Whi + _gb);                                   \
            cp16(_base + B_LO + _so, Wlo + _gb);                                   \
        }                                                                          \
        cp_commit();                                                               \
    } while (0)

    ISSUE(0);
    ISSUE(1);

    float acc[2][8][4];
#pragma unroll
    for (int i = 0; i < 2; ++i)
#pragma unroll
        for (int j = 0; j < 8; ++j)
#pragma unroll
            for (int r = 0; r < 4; ++r) acc[i][j][r] = 0.0f;

    const int wn = (wid & 3) * 32;       // warp batch-row base (32 n rows)
    const int wm = (wid >> 2) * 64;      // warp hidden-col base (64 m cols)
    const int gid = l >> 2, tig = l & 3;

    // ldmatrix per-lane logical (row, chunk) -> swizzled byte offsets
    const int r3 = l & 3;
    const uint32_t abase = (uint32_t)(wn + (l & 15)) * 64;                        // + s*1024
    const uint32_t bbase = (uint32_t)(wm + (l & 7) + ((l >> 4) & 1) * 8) * 64;    // + g*1024
    const int qa = (l >> 4) & 1;
    const int qb = (l >> 3) & 1;
    const uint32_t aswz[2] = { (uint32_t)((qa ^ r3) << 4), (uint32_t)(((qa + 2) ^ r3) << 4) };
    const uint32_t bswz[2] = { (uint32_t)((qb ^ r3) << 4), (uint32_t)(((qb + 2) ^ r3) << 4) };

    for (int c = 0; c < NC; ++c) {
        if (c + 1 < NC) cp_wait1(); else cp_wait0();
        __syncthreads();
        if (c + 2 < NC) ISSUE(c + 2);   // buffer (c+2)%3 freed by the sync above

        const uint32_t stg = sb + OFF_T + (c % NSTAGE) * STAGE;
        const uint32_t astg = stg + A_HI + abase;
        const uint32_t bstg = stg + B_HI + bbase;

#pragma unroll
        for (int k16 = 0; k16 < 2; ++k16) {
            // A fragments for this k16: hi and lo planes, both n subtiles.
            unsigned ah[2][4], al[2][4];
#pragma unroll
            for (int s = 0; s < 2; ++s) {
                ldsm4(ah[s], astg + s * 1024 + aswz[k16]);
                ldsm4(al[s], astg + (A_LO - A_HI) + s * 1024 + aswz[k16]);
            }
            // Per-g software pipeline: prefetch g+1's W fragments before g's mma.
            unsigned bwA[4], blA[4], bwB[4], blB[4];
            ldsm4(bwA, bstg + bswz[k16]);
            ldsm4(blA, bstg + (B_LO - B_HI) + bswz[k16]);
#pragma unroll
            for (int g = 0; g < 4; ++g) {
                unsigned* bw  = (g & 1) ? bwB : bwA;
                unsigned* bl  = (g & 1) ? blB : blA;
                unsigned* bwn = (g & 1) ? bwA : bwB;
                unsigned* bln = (g & 1) ? blA : blB;
                if (g < 3) {
                    ldsm4(bwn, bstg + (g + 1) * 1024 + bswz[k16]);
                    ldsm4(bln, bstg + (B_LO - B_HI) + (g + 1) * 1024 + bswz[k16]);
                }
                // pass 1: Hhi * Whi   (per-output order p1,p2,p3 preserved)
                mma16816(acc[0][2 * g],     ah[0], &bw[0]);
                mma16816(acc[0][2 * g + 1], ah[0], &bw[2]);
                mma16816(acc[1][2 * g],     ah[1], &bw[0]);
                mma16816(acc[1][2 * g + 1], ah[1], &bw[2]);
                // pass 2: Hhi * Wlo
                mma16816(acc[0][2 * g],     ah[0], &bl[0]);
                mma16816(acc[0][2 * g + 1], ah[0], &bl[2]);
                mma16816(acc[1][2 * g],     ah[1], &bl[0]);
                mma16816(acc[1][2 * g + 1], ah[1], &bl[2]);
                // pass 3: Hlo * Whi
                mma16816(acc[0][2 * g],     al[0], &bw[0]);
                mma16816(acc[0][2 * g + 1], al[0], &bw[2]);
                mma16816(acc[1][2 * g],     al[1], &bw[0]);
                mma16816(acc[1][2 * g + 1], al[1], &bw[2]);
            }
        }
    }
#undef ISSUE

    // ---- epilogue: z[n][m] = acc + wx[m]*x[n] + bh[m]; tanh; split; direct store ----
    {
        const float* xs  = (const float*)(smem + OFF_XS);
        const float* wxs = (const float*)(smem + OFF_WX);
        const float* bhs = (const float*)(smem + OFF_BH);
#pragma unroll
        for (int s = 0; s < 2; ++s) {
#pragma unroll
            for (int nt = 0; nt < 8; ++nt) {
                const int m = wm + nt * 8 + 2 * tig;          // even
                const float wx0 = wxs[m],     bb0 = bhs[m];
                const float wx1 = wxs[m + 1], bb1 = bhs[m + 1];
#pragma unroll
                for (int half = 0; half < 2; ++half) {
                    const int n = wn + s * 16 + gid + half * 8;
                    const float xn = xs[n];
                    float v0 = tanh_fast(acc[s][nt][2 * half + 0] + fmaf(wx0, xn, bb0));
                    float v1 = tanh_fast(acc[s][nt][2 * half + 1] + fmaf(wx1, xn, bb1));
                    __nv_bfloat162 ph, pl;
                    ph.x = __float2bfloat16(v0);
                    ph.y = __float2bfloat16(v1);
                    pl.x = __float2bfloat16(v0 - __bfloat162float(ph.x));
                    pl.y = __float2bfloat16(v1 - __bfloat162float(ph.y));
                    size_t gi = (size_t)(n0 + n) * HD + m0 + m;
                    *(__nv_bfloat162*)(Ohi + gi) = ph;
                    *(__nv_bfloat162*)(Olo + gi) = pl;
                }
            }
        }
    }
}

// ---------------------------------------------------------------------------
// Output projection: out[n][c] = sum_k (hi+lo)[n][k] * Why[k][c] + bp[c]
// ---------------------------------------------------------------------------
__global__ void __launch_bounds__(256)
rnn_out(const __nv_bfloat16* __restrict__ Hhi, const __nv_bfloat16* __restrict__ Hlo,
        const float* __restrict__ Why, const float* __restrict__ bp,
        float* __restrict__ out)
{
    const int wid = threadIdx.x >> 5, lane = threadIdx.x & 31;
    const int n = blockIdx.x * 8 + wid;
    float acc[CD];
#pragma unroll
    for (int c = 0; c < CD; ++c) acc[c] = 0.0f;

    for (int it = 0; it < 8; ++it) {
        int k0 = (it * 32 + lane) * 8;
        uint4 ph = *(const uint4*)&Hhi[(size_t)n * HD + k0];
        uint4 pl = *(const uint4*)&Hlo[(size_t)n * HD + k0];
        const unsigned rh[4] = {ph.x, ph.y, ph.z, ph.w};
        const unsigned rl[4] = {pl.x, pl.y, pl.z, pl.w};
#pragma unroll
        for (int kk = 0; kk < 4; ++kk) {
            __nv_bfloat162 h2 = *reinterpret_cast<const __nv_bfloat162*>(&rh[kk]);
            __nv_bfloat162 l2 = *reinterpret_cast<const __nv_bfloat162*>(&rl[kk]);
            float h0 = __bfloat162float(h2.x) + __bfloat162float(l2.x);
            float h1 = __bfloat162float(h2.y) + __bfloat162float(l2.y);
            const float* w0 = Why + (size_t)(k0 + 2 * kk) * CD;
            const float* w1 = w0 + CD;
#pragma unroll
            for (int c = 0; c < CD; ++c) {
                acc[c] = fmaf(h0, __ldg(w0 + c), acc[c]);
                acc[c] = fmaf(h1, __ldg(w1 + c), acc[c]);
            }
        }
    }
#pragma unroll
    for (int o = 16; o > 0; o >>= 1)
#pragma unroll
        for (int c = 0; c < CD; ++c)
            acc[c] += __shfl_xor_sync(0xFFFFFFFFu, acc[c], o);
    if (lane == 0) {
#pragma unroll
        for (int c = 0; c < CD; ++c) out[(size_t)n * CD + c] = acc[c] + bp[c];
    }
}

// ---------------------------------------------------------------------------
extern "C" void kernel_launch(void* const* d_in, const int* in_sizes, int n_in,
                              void* d_out, int out_size)
{
    const float* x   = (const float*)d_in[0];
    const float* Whx = (const float*)d_in[1];
    const float* Whh = (const float*)d_in[2];
    const float* Why = (const float*)d_in[3];
    const float* bh  = (const float*)d_in[4];
    const float* bp  = (const float*)d_in[5];
    float* out = (float*)d_out;

    cudaFuncSetAttribute(rnn_step, cudaFuncAttributeMaxDynamicSharedMemorySize, SMEM_TOTAL);

    __nv_bfloat16 *Whi = nullptr, *Wlo = nullptr, *Hb = nullptr;
    cudaGetSymbolAddress((void**)&Whi, g_Whi);
    cudaGetSymbolAddress((void**)&Wlo, g_Wlo);
    cudaGetSymbolAddress((void**)&Hb, g_Hbuf);
    const size_t S = (size_t)BD * HD;

    __nv_bfloat16* curHi = Hb;           // buf0
    __nv_bfloat16* curLo = Hb + S;
    __nv_bfloat16* nxtHi = Hb + 2 * S;   // buf1
    __nv_bfloat16* nxtLo = Hb + 3 * S;

    split_whh<<<(HD * HD) / 256, 256>>>(Whh, Whi, Wlo);
    rnn_first<<<dim3(HD / 256, BD), 256>>>(x, Whx, bh, curHi, curLo);

    for (int t = 1; t < TD; ++t) {
        rnn_step<<<dim3(16, 16), 256, SMEM_TOTAL>>>(Whi, Wlo, curHi, curLo,
                                                    nxtHi, nxtLo, x, Whx, bh, t);
        __nv_bfloat16* th = curHi; curHi = nxtHi; nxtHi = th;
        __nv_bfloat16* tl = curLo; curLo = nxtLo; nxtLo = tl;
    }

    rnn_out<<<BD / 8, 256>>>(curHi, curLo, Why, bp, out);
}

// round 17
// speedup vs baseline: 5.6451x; 1.4048x over previous
#include <cuda_runtime.h>
#include <cuda_fp16.h>
#include <cstdint>

// VanillaRNN: h_t = tanh(W_hh @ h_{t-1} + W_hx x_t + b_h); out = W_hy^T h_T + b_p
// H = B = 2048, T = 64, C = 10.
//
// 2-pass fp16 scheme: W quantized ONCE to a single fp16 plane Wf (exact
// trajectory of the nearby RNN W' = fp16(W); delta ~2^-11 relative).
// h kept as fp16 (hi,lo) pair scaled by 64 (avoids fp16 subnormals in lo):
//   z = (hi@Wf + lo@Wf) / 64,  fp32 accumulation inside mma.
// GEMM orientation: C[n][m] = sum_k hT[n][k] * Wf[m][k]; output fragments land
// in [n][m] = next step's A layout (no transpose). mma.m16n8k16.f32.f16.f16.f32.
// 3-stage cp.async pipeline, one barrier per chunk, pitch-64 XOR-16 swizzle,
// per-g W-fragment prefetch under the mma stream.

#define HD 2048
#define BD 2048
#define TD 64
#define CD 10

#define NC (HD / 32)       // 64 k-chunks of 32 elements
#define HSCALE 64.0f
#define HINV   (1.0f / 64.0f)

// smem layout (dynamic)
#define OFF_XS   0         // 128 floats: x[n0..n0+127][t]
#define OFF_WX   512       // 128 floats: Whx[m0..]
#define OFF_BH   1024      // 128 floats: bh[m0..]
#define OFF_T    2048      // tile buffers
#define PLANE    8192      // 128 rows * 64B (XOR-swizzled chunks)
#define STAGE    24576     // Ahi | Alo | Wf
#define A_HI     0
#define A_LO     8192
#define B_W      16384
#define NSTAGE   3
#define SMEM_TOTAL (OFF_T + NSTAGE * STAGE)   // 75776

// Scratch planes (no allocation allowed)
__device__ __half g_Wf[(size_t)HD * HD];
__device__ __half g_Hbuf[4][(size_t)BD * HD];   // [buf0 hi, buf0 lo, buf1 hi, buf1 lo]

// ---------------------------------------------------------------------------
__device__ __forceinline__ uint32_t smem_u32(const void* p) {
    uint32_t a;
    asm("{ .reg .u64 t; cvta.to.shared.u64 t, %1; cvt.u32.u64 %0, t; }" : "=r"(a) : "l"(p));
    return a;
}
__device__ __forceinline__ void cp16(uint32_t s, const void* g) {
    asm volatile("cp.async.cg.shared.global [%0], [%1], 16;" :: "r"(s), "l"(g));
}
__device__ __forceinline__ void cp_commit() {
    asm volatile("cp.async.commit_group;" ::: "memory");
}
__device__ __forceinline__ void cp_wait1() {
    asm volatile("cp.async.wait_group 1;" ::: "memory");
}
__device__ __forceinline__ void cp_wait0() {
    asm volatile("cp.async.wait_group 0;" ::: "memory");
}
__device__ __forceinline__ void ldsm4(unsigned* r, uint32_t a) {
    asm volatile("ldmatrix.sync.aligned.m8n8.x4.shared.b16 {%0,%1,%2,%3}, [%4];"
                 : "=r"(r[0]), "=r"(r[1]), "=r"(r[2]), "=r"(r[3]) : "r"(a));
}
__device__ __forceinline__ void mma16816(float* c, const unsigned* a, const unsigned* b) {
    asm volatile("mma.sync.aligned.m16n8k16.row.col.f32.f16.f16.f32 "
                 "{%0,%1,%2,%3}, {%4,%5,%6,%7}, {%8,%9}, {%0,%1,%2,%3};"
                 : "+f"(c[0]), "+f"(c[1]), "+f"(c[2]), "+f"(c[3])
                 : "r"(a[0]), "r"(a[1]), "r"(a[2]), "r"(a[3]), "r"(b[0]), "r"(b[1]));
}

// MUFU-free tanh (pure FMA/ALU).
__device__ __forceinline__ float tanh_fast(float x) {
    float t = fminf(fabsf(x) * 2.885390081777927f, 60.0f);
    float r = t + 12582912.0f;
    int   ni = __float_as_int(r) - 0x4B400000;
    float f = t - (r - 12582912.0f);
    float p = 1.5403530394e-4f;
    p = fmaf(p, f, 1.3333558146e-3f);
    p = fmaf(p, f, 9.6181291076e-3f);
    p = fmaf(p, f, 5.5504108664e-2f);
    p = fmaf(p, f, 2.4022650696e-1f);
    p = fmaf(p, f, 6.9314718056e-1f);
    p = fmaf(p, f, 1.0f);
    float u = __int_as_float(__float_as_int(p) + (ni << 23));
    float d = u + 1.0f;
    float w = __int_as_float(0x7EF311C3 - __float_as_int(d));
    w = w * fmaf(-d, w, 2.0f);
    w = w * fmaf(-d, w, 2.0f);
    w = w * fmaf(-d, w, 2.0f);
    float y = fmaf(-2.0f, w, 1.0f);
    return __int_as_float(__float_as_int(y) | (__float_as_int(x) & 0x80000000));
}

// split v*64 into fp16 hi + lo (all values in fp16 normal range)
__device__ __forceinline__ void split_h(float v, __half* hi, __half* lo) {
    float vs = v * HSCALE;
    __half h = __float2half(vs);
    *hi = h;
    *lo = __float2half(vs - __half2float(h));
}

// ---------------------------------------------------------------------------
// Prep kernels
// ---------------------------------------------------------------------------
__global__ void quant_whh(const float* __restrict__ W, __half* __restrict__ Wf) {
    size_t e = (size_t)blockIdx.x * 256 + threadIdx.x;
    Wf[e] = __float2half(W[e]);
}

__global__ void rnn_first(const float* __restrict__ x, const float* __restrict__ Whx,
                          const float* __restrict__ bh,
                          __half* __restrict__ Ohi, __half* __restrict__ Olo) {
    int i = blockIdx.x * 256 + threadIdx.x;
    int n = blockIdx.y;
    float v = tanh_fast(fmaf(Whx[i], x[(size_t)n * TD], bh[i]));
    __half hi, lo;
    split_h(v, &hi, &lo);
    Ohi[(size_t)n * HD + i] = hi;
    Olo[(size_t)n * HD + i] = lo;
}

// ---------------------------------------------------------------------------
// Main step. Grid (16 m-tiles, 16 n-tiles), 256 threads, 2 CTAs/SM.
// Swizzle: element 16B-chunk q of row r stored at r*64 + (q ^ (r&3))*16.
// ---------------------------------------------------------------------------
extern __shared__ __align__(128) char smem[];

__global__ void __launch_bounds__(256, 2)
rnn_step(const __half* __restrict__ Wf,
         const __half* __restrict__ Hhi, const __half* __restrict__ Hlo,
         __half* __restrict__ Ohi, __half* __restrict__ Olo,
         const float* __restrict__ x, const float* __restrict__ Whx,
         const float* __restrict__ bhv, int t)
{
    const uint32_t sb = smem_u32(smem);
    const int tid = threadIdx.x;
    const int wid = tid >> 5, l = tid & 31;
    const int m0 = blockIdx.x * 128;   // hidden (GEMM N dim)
    const int n0 = blockIdx.y * 128;   // batch  (GEMM M dim)

    if (tid < 128) {
        ((float*)(smem + OFF_XS))[tid] = x[(size_t)(n0 + tid) * TD + t];
        ((float*)(smem + OFF_WX))[tid] = Whx[m0 + tid];
        ((float*)(smem + OFF_BH))[tid] = bhv[m0 + tid];
    }

    // A tiles <- h hi/lo (rows n0+row); B tile <- Wf (rows m0+row)
#define ISSUE(c)                                                                   \
    do {                                                                           \
        const uint32_t _base = sb + OFF_T + ((c) % NSTAGE) * STAGE;                \
        _Pragma("unroll")                                                          \
        for (int _i = 0; _i < 2; ++_i) {                                           \
            int _idx = tid + _i * 256;                                             \
            int _row = _idx >> 2, _q = _idx & 3;                                   \
            uint32_t _so = _row * 64 + ((_q ^ (_row & 3)) << 4);                   \
            size_t _ga = (size_t)(n0 + _row) * HD + (c) * 32 + _q * 8;             \
            size_t _gb = (size_t)(m0 + _row) * HD + (c) * 32 + _q * 8;             \
            cp16(_base + A_HI + _so, Hhi + _ga);                                   \
            cp16(_base + A_LO + _so, Hlo + _ga);                                   \
            cp16(_base + B_W + _so, Wf + _gb);                                     \
        }                                                                          \
        cp_commit();                                                               \
    } while (0)

    ISSUE(0);
    ISSUE(1);

    float acc[2][8][4];
#pragma unroll
    for (int i = 0; i < 2; ++i)
#pragma unroll
        for (int j = 0; j < 8; ++j)
#pragma unroll
            for (int r = 0; r < 4; ++r) acc[i][j][r] = 0.0f;

    const int wn = (wid & 3) * 32;       // warp batch-row base (32 n rows)
    const int wm = (wid >> 2) * 64;      // warp hidden-col base (64 m cols)
    const int gid = l >> 2, tig = l & 3;

    // ldmatrix per-lane logical (row, chunk) -> swizzled byte offsets
    const int r3 = l & 3;
    const uint32_t abase = (uint32_t)(wn + (l & 15)) * 64;                        // + s*1024
    const uint32_t bbase = (uint32_t)(wm + (l & 7) + ((l >> 4) & 1) * 8) * 64;    // + g*1024
    const int qa = (l >> 4) & 1;
    const int qb = (l >> 3) & 1;
    const uint32_t aswz[2] = { (uint32_t)((qa ^ r3) << 4), (uint32_t)(((qa + 2) ^ r3) << 4) };
    const uint32_t bswz[2] = { (uint32_t)((qb ^ r3) << 4), (uint32_t)(((qb + 2) ^ r3) << 4) };

    for (int c = 0; c < NC; ++c) {
        if (c + 1 < NC) cp_wait1(); else cp_wait0();
        __syncthreads();
        if (c + 2 < NC) ISSUE(c + 2);   // buffer (c+2)%3 freed by the sync above

        const uint32_t stg = sb + OFF_T + (c % NSTAGE) * STAGE;
        const uint32_t astg = stg + A_HI + abase;
        const uint32_t bstg = stg + B_W + bbase;

#pragma unroll
        for (int k16 = 0; k16 < 2; ++k16) {
            // A fragments for this k16: hi and lo planes, both n subtiles.
            unsigned ah[2][4], al[2][4];
#pragma unroll
            for (int s = 0; s < 2; ++s) {
                ldsm4(ah[s], astg + s * 1024 + aswz[k16]);
                ldsm4(al[s], astg + (A_LO - A_HI) + s * 1024 + aswz[k16]);
            }
            // Per-g software pipeline: prefetch g+1's W fragments before g's mma.
            unsigned bwA[4], bwB[4];
            ldsm4(bwA, bstg + bswz[k16]);
#pragma unroll
            for (int g = 0; g < 4; ++g) {
                unsigned* bw  = (g & 1) ? bwB : bwA;
                unsigned* bwn = (g & 1) ? bwA : bwB;
                if (g < 3) ldsm4(bwn, bstg + (g + 1) * 1024 + bswz[k16]);
                // pass 1: hi * Wf
                mma16816(acc[0][2 * g],     ah[0], &bw[0]);
                mma16816(acc[0][2 * g + 1], ah[0], &bw[2]);
                mma16816(acc[1][2 * g],     ah[1], &bw[0]);
                mma16816(acc[1][2 * g + 1], ah[1], &bw[2]);
                // pass 2: lo * Wf
                mma16816(acc[0][2 * g],     al[0], &bw[0]);
                mma16816(acc[0][2 * g + 1], al[0], &bw[2]);
                mma16816(acc[1][2 * g],     al[1], &bw[0]);
                mma16816(acc[1][2 * g + 1], al[1], &bw[2]);
            }
        }
    }
#undef ISSUE

    // ---- epilogue: z = acc/64 + wx[m]*x[n] + bh[m]; tanh; split*64; store ----
    {
        const float* xs  = (const float*)(smem + OFF_XS);
        const float* wxs = (const float*)(smem + OFF_WX);
        const float* bhs = (const float*)(smem + OFF_BH);
#pragma unroll
        for (int s = 0; s < 2; ++s) {
#pragma unroll
            for (int nt = 0; nt < 8; ++nt) {
                const int m = wm + nt * 8 + 2 * tig;          // even
                const float wx0 = wxs[m],     bb0 = bhs[m];
                const float wx1 = wxs[m + 1], bb1 = bhs[m + 1];
#pragma unroll
                for (int half = 0; half < 2; ++half) {
                    const int n = wn + s * 16 + gid + half * 8;
                    const float xn = xs[n];
                    float v0 = tanh_fast(fmaf(acc[s][nt][2 * half + 0], HINV,
                                              fmaf(wx0, xn, bb0)));
                    float v1 = tanh_fast(fmaf(acc[s][nt][2 * half + 1], HINV,
                                              fmaf(wx1, xn, bb1)));
                    __half h0, l0, h1, l1;
                    split_h(v0, &h0, &l0);
                    split_h(v1, &h1, &l1);
                    __half2 ph = __halves2half2(h0, h1);
                    __half2 pl = __halves2half2(l0, l1);
                    size_t gi = (size_t)(n0 + n) * HD + m0 + m;
                    *(__half2*)(Ohi + gi) = ph;
                    *(__half2*)(Olo + gi) = pl;
                }
            }
        }
    }
}

// ---------------------------------------------------------------------------
// Output projection: out[n][c] = sum_k ((hi+lo)/64)[n][k] * Why[k][c] + bp[c]
// ---------------------------------------------------------------------------
__global__ void __launch_bounds__(256)
rnn_out(const __half* __restrict__ Hhi, const __half* __restrict__ Hlo,
        const float* __restrict__ Why, const float* __restrict__ bp,
        float* __restrict__ out)
{
    const int wid = threadIdx.x >> 5, lane = threadIdx.x & 31;
    const int n = blockIdx.x * 8 + wid;
    float acc[CD];
#pragma unroll
    for (int c = 0; c < CD; ++c) acc[c] = 0.0f;

    for (int it = 0; it < 8; ++it) {
        int k0 = (it * 32 + lane) * 8;
        uint4 ph = *(const uint4*)&Hhi[(size_t)n * HD + k0];
        uint4 pl = *(const uint4*)&Hlo[(size_t)n * HD + k0];
        const unsigned rh[4] = {ph.x, ph.y, ph.z, ph.w};
        const unsigned rl[4] = {pl.x, pl.y, pl.z, pl.w};
#pragma unroll
        for (int kk = 0; kk < 4; ++kk) {
            __half2 h2 = *reinterpret_cast<const __half2*>(&rh[kk]);
            __half2 l2 = *reinterpret_cast<const __half2*>(&rl[kk]);
            float h0 = (__half2float(h2.x) + __half2float(l2.x)) * HINV;
            float h1 = (__half2float(h2.y) + __half2float(l2.y)) * HINV;
            const float* w0 = Why + (size_t)(k0 + 2 * kk) * CD;
            const float* w1 = w0 + CD;
#pragma unroll
            for (int c = 0; c < CD; ++c) {
                acc[c] = fmaf(h0, __ldg(w0 + c), acc[c]);
                acc[c] = fmaf(h1, __ldg(w1 + c), acc[c]);
            }
        }
    }
#pragma unroll
    for (int o = 16; o > 0; o >>= 1)
#pragma unroll
        for (int c = 0; c < CD; ++c)
            acc[c] += __shfl_xor_sync(0xFFFFFFFFu, acc[c], o);
    if (lane == 0) {
#pragma unroll
        for (int c = 0; c < CD; ++c) out[(size_t)n * CD + c] = acc[c] + bp[c];
    }
}

// ---------------------------------------------------------------------------
extern "C" void kernel_launch(void* const* d_in, const int* in_sizes, int n_in,
                              void* d_out, int out_size)
{
    const float* x   = (const float*)d_in[0];
    const float* Whx = (const float*)d_in[1];
    const float* Whh = (const float*)d_in[2];
    const float* Why = (const float*)d_in[3];
    const float* bh  = (const float*)d_in[4];
    const float* bp  = (const float*)d_in[5];
    float* out = (float*)d_out;

    cudaFuncSetAttribute(rnn_step, cudaFuncAttributeMaxDynamicSharedMemorySize, SMEM_TOTAL);

    __half *Wf = nullptr, *Hb = nullptr;
    cudaGetSymbolAddress((void**)&Wf, g_Wf);
    cudaGetSymbolAddress((void**)&Hb, g_Hbuf);
    const size_t S = (size_t)BD * HD;

    __half* curHi = Hb;           // buf0
    __half* curLo = Hb + S;
    __half* nxtHi = Hb + 2 * S;   // buf1
    __half* nxtLo = Hb + 3 * S;

    quant_whh<<<(HD * HD) / 256, 256>>>(Whh, Wf);
    rnn_first<<<dim3(HD / 256, BD), 256>>>(x, Whx, bh, curHi, curLo);

    for (int t = 1; t < TD; ++t) {
        rnn_step<<<dim3(16, 16), 256, SMEM_TOTAL>>>(Wf, curHi, curLo,
                                                    nxtHi, nxtLo, x, Whx, bh, t);
        __half* th = curHi; curHi = nxtHi; nxtHi = th;
        __half* tl = curLo; curLo = nxtLo; nxtLo = tl;
    }

    rnn_out<<<BD / 8, 256>>>(curHi, curLo, Why, bp, out);
}